// round 6
// baseline (speedup 1.0000x reference)
#include <cuda_runtime.h>
#include <cuda_bf16.h>
#include <math.h>
#include <stdint.h>

#define SS 128
#define BB 128
#define VV 10000
#define HH 512
#define EE 512
#define KDIM 512

// ---------------- scratch (device globals: no allocations allowed) ----------
__device__ float g_P[VV * HH];         // scale * emb @ W0_x^T
__device__ float g_h0[2][BB * HH];     // ping-pong layer-0 hidden
__device__ float g_h1[2][BB * HH];     // ping-pong layer-1 hidden
__device__ unsigned int g_sync;        // grid barrier counter
// bf16 hi/lo split operands for tensor GEMMs
__device__ __nv_bfloat16 g_Thi[SS * BB * HH];
__device__ __nv_bfloat16 g_Tlo[SS * BB * HH];
__device__ __nv_bfloat16 g_Whi[VV * HH];
__device__ __nv_bfloat16 g_Wlo[VV * HH];
__device__ __nv_bfloat16 g_Ehi[VV * EE];
__device__ __nv_bfloat16 g_Elo[VV * EE];
__device__ __nv_bfloat16 g_Xhi[HH * EE];
__device__ __nv_bfloat16 g_Xlo[HH * EE];

// ============================ helpers ========================================
__device__ __forceinline__ uint32_t smem_u32(const void* p) {
    uint32_t a;
    asm("{ .reg .u64 t; cvta.to.shared.u64 t, %1; cvt.u32.u64 %0, t; }"
        : "=r"(a) : "l"(p));
    return a;
}

__device__ __forceinline__ void ldm_x4(uint32_t addr, uint32_t r[4]) {
    asm volatile("ldmatrix.sync.aligned.m8n8.x4.shared.b16 {%0,%1,%2,%3}, [%4];"
                 : "=r"(r[0]), "=r"(r[1]), "=r"(r[2]), "=r"(r[3]) : "r"(addr));
}

__device__ __forceinline__ void mma_bf16(float c[4], const uint32_t a[4],
                                         uint32_t b0, uint32_t b1) {
    asm volatile(
        "mma.sync.aligned.m16n8k16.row.col.f32.bf16.bf16.f32 "
        "{%0,%1,%2,%3}, {%4,%5,%6,%7}, {%8,%9}, {%0,%1,%2,%3};"
        : "+f"(c[0]), "+f"(c[1]), "+f"(c[2]), "+f"(c[3])
        : "r"(a[0]), "r"(a[1]), "r"(a[2]), "r"(a[3]), "r"(b0), "r"(b1));
}

__device__ __forceinline__ void fma4(float4& acc, const float4& a, const float4& b) {
    acc.x = fmaf(a.x, b.x, acc.x);
    acc.y = fmaf(a.y, b.y, acc.y);
    acc.z = fmaf(a.z, b.z, acc.z);
    acc.w = fmaf(a.w, b.w, acc.w);
}

// =================== bf16-split HMMA GEMM ====================================
#define BK 32
#define ROWB 80
#define TILE_SB (128 * ROWB)
#define STAGE_SB (4 * TILE_SB)
#define GEMM_SMEM (2 * STAGE_SB)
#define KT_N (KDIM / BK)

__global__ __launch_bounds__(256, 1)
void gemm_hmma(const __nv_bfloat16* __restrict__ Ahi,
               const __nv_bfloat16* __restrict__ Alo,
               const __nv_bfloat16* __restrict__ Bhi,
               const __nv_bfloat16* __restrict__ Blo,
               int M, int N, float* __restrict__ C, int ldc,
               const float* __restrict__ bias) {
    extern __shared__ char smem[];
    const uint32_t sb = smem_u32(smem);
    const int tid = threadIdx.x;
    const int wid = tid >> 5, lid = tid & 31;
    const int wm = wid & 3, wn = wid >> 2;
    const int nb = blockIdx.x, mb = blockIdx.y;

    const __nv_bfloat16* __restrict__ srcs[4] = {Ahi, Alo, Bhi, Blo};

    float acc[2][8][4];
#pragma unroll
    for (int i = 0; i < 2; i++)
#pragma unroll
        for (int j = 0; j < 8; j++)
#pragma unroll
            for (int q = 0; q < 4; q++) acc[i][j][q] = 0.0f;

    auto load_stage = [&](int st, int kt) {
#pragma unroll
        for (int t = 0; t < 4; t++) {
#pragma unroll
            for (int i = 0; i < 2; i++) {
                const int idx = tid + i * 256;
                const int row = idx >> 2, ch = idx & 3;
                const long long grow =
                    (t < 2) ? (long long)mb * 128 + row : (long long)nb * 128 + row;
                const bool ok = (t < 2) ? (grow < M) : (grow < N);
                const __nv_bfloat16* src = srcs[t] + grow * KDIM + kt * BK + ch * 8;
                const uint32_t dst = sb + st * STAGE_SB + t * TILE_SB + row * ROWB + ch * 16;
                const int sz = ok ? 16 : 0;
                asm volatile("cp.async.cg.shared.global [%0], [%1], 16, %2;"
                             :: "r"(dst), "l"(src), "r"(sz) : "memory");
            }
        }
    };

    const int lr = lid & 15;
    const int lc = lid >> 4;

    load_stage(0, 0);
    asm volatile("cp.async.commit_group;" ::: "memory");

    for (int kt = 0; kt < KT_N; kt++) {
        const int st = kt & 1;
        if (kt + 1 < KT_N) {
            load_stage(st ^ 1, kt + 1);
            asm volatile("cp.async.commit_group;" ::: "memory");
            asm volatile("cp.async.wait_group 1;" ::: "memory");
        } else {
            asm volatile("cp.async.wait_group 0;" ::: "memory");
        }
        __syncthreads();

        const uint32_t stg = sb + st * STAGE_SB;
        const uint32_t aBaseHi = stg + 0 * TILE_SB;
        const uint32_t aBaseLo = stg + 1 * TILE_SB;
        const uint32_t bBaseHi = stg + 2 * TILE_SB;
        const uint32_t bBaseLo = stg + 3 * TILE_SB;

#pragma unroll
        for (int k16 = 0; k16 < 2; k16++) {
            const uint32_t koff = k16 * 32 + lc * 16;

            uint32_t ahi[2][4], alo[2][4];
#pragma unroll
            for (int mf = 0; mf < 2; mf++) {
                const uint32_t roff = (uint32_t)(wm * 32 + mf * 16 + lr) * ROWB + koff;
                ldm_x4(aBaseHi + roff, ahi[mf]);
                ldm_x4(aBaseLo + roff, alo[mf]);
            }
#pragma unroll
            for (int reg = 0; reg < 4; reg++) {
                const uint32_t roff = (uint32_t)(wn * 64 + reg * 16 + lr) * ROWB + koff;
                uint32_t bh[4], bl2[4];
                ldm_x4(bBaseHi + roff, bh);
                ldm_x4(bBaseLo + roff, bl2);
#pragma unroll
                for (int mf = 0; mf < 2; mf++) {
                    mma_bf16(acc[mf][reg * 2 + 0], ahi[mf], bh[0], bh[2]);
                    mma_bf16(acc[mf][reg * 2 + 0], ahi[mf], bl2[0], bl2[2]);
                    mma_bf16(acc[mf][reg * 2 + 0], alo[mf], bh[0], bh[2]);
                    mma_bf16(acc[mf][reg * 2 + 1], ahi[mf], bh[1], bh[3]);
                    mma_bf16(acc[mf][reg * 2 + 1], ahi[mf], bl2[1], bl2[3]);
                    mma_bf16(acc[mf][reg * 2 + 1], alo[mf], bh[1], bh[3]);
                }
            }
        }
        __syncthreads();
    }

    const int lr4 = lid >> 2;
    const int lc2 = (lid & 3) * 2;
#pragma unroll
    for (int mf = 0; mf < 2; mf++) {
#pragma unroll
        for (int nf = 0; nf < 8; nf++) {
            const int m = mb * 128 + wm * 32 + mf * 16 + lr4;
            const int n = nb * 128 + wn * 64 + nf * 8 + lc2;
            if (n >= N) continue;
            float b0 = 0.f, b1 = 0.f;
            if (bias) { b0 = bias[n]; b1 = bias[n + 1]; }
            if (m < M) {
                float2 v = make_float2(acc[mf][nf][0] + b0, acc[mf][nf][1] + b1);
                *reinterpret_cast<float2*>(C + (long long)m * ldc + n) = v;
            }
            if (m + 8 < M) {
                float2 v = make_float2(acc[mf][nf][2] + b0, acc[mf][nf][3] + b1);
                *reinterpret_cast<float2*>(C + (long long)(m + 8) * ldc + n) = v;
            }
        }
    }
}

// =================== persistent recurrence kernel (chunked) ==================
#define RNN_CTAS 128
#define RNN_THR 256
#define WSTR 516
#define HSTR 132
#define OFF_W0 0
#define OFF_WL (16 * WSTR)
#define OFF_WX (32 * WSTR)
#define OFF_HS (48 * WSTR)
#define RNN_SMEM ((48 * WSTR + 32 * HSTR) * 4)

__device__ __forceinline__ void grid_bar(unsigned int target) {
    __syncthreads();
    if (threadIdx.x == 0) {
        unsigned int* p = &g_sync;
        asm volatile("red.release.gpu.global.add.u32 [%0], 1;" :: "l"(p) : "memory");
        unsigned int v;
        do {
            asm volatile("ld.acquire.gpu.global.u32 %0, [%1];" : "=r"(v) : "l"(p) : "memory");
        } while (v < target);
    }
    __syncthreads();
}

__global__ __launch_bounds__(RNN_THR, 1)
void rnn_persist(int p_start, int p_end,
                 const int* __restrict__ inputs,
                 const float* __restrict__ W0,
                 const float* __restrict__ b0,
                 const float* __restrict__ Wl,
                 const float* __restrict__ bl) {
    extern __shared__ float sm[];
    const int tid = threadIdx.x;
    const int bg = blockIdx.x >> 5;
    const int cg = blockIdx.x & 31;
    const int cbase = cg * 16;

    for (int i = tid; i < 16 * 512; i += RNN_THR) {
        const int r = i >> 9, k = i & 511;
        const int gc = cbase + r;
        sm[OFF_W0 + r * WSTR + k] = W0[gc * 1024 + k];
        sm[OFF_WL + r * WSTR + k] = Wl[gc * 1024 + k];
        sm[OFF_WX + r * WSTR + k] = Wl[gc * 1024 + 512 + k];
    }
    __syncthreads();

    const int c_l = tid & 15;
    const int rg = tid >> 4;
    const int col = cbase + c_l;
    const int r0 = rg * 2, r1 = rg * 2 + 1;
    const int gb0 = bg * 32 + r0, gb1 = bg * 32 + r1;
    const float b0c = b0[col];
    const float blc = bl[col];
    float* const hs = sm + OFF_HS;

    for (int p = p_start; p < p_end; p++) {
        const float* __restrict__ h0old = g_h0[(p + 1) & 1];
        const float* __restrict__ h1prev = g_h1[p & 1];
        float* __restrict__ h0new = g_h0[p & 1];
        float* __restrict__ h1new = g_h1[(p + 1) & 1];

        float4 a00 = make_float4(0, 0, 0, 0), a01 = a00;
        float4 a10 = a00, a11 = a00;

#pragma unroll 1
        for (int ch = 0; ch < 4; ch++) {
#pragma unroll
            for (int j = 0; j < 4; j++) {
                const int idx = tid + j * 256;
                const int rr = idx >> 5, cc = idx & 31;
                float4 v = __ldcg(reinterpret_cast<const float4*>(
                    h0old + (long long)(bg * 32 + rr) * HH + ch * 128 + cc * 4));
                *reinterpret_cast<float4*>(hs + rr * HSTR + cc * 4) = v;
            }
            __syncthreads();
            const float* w0r = sm + OFF_W0 + c_l * WSTR + ch * 128;
            const float* wxr = sm + OFF_WX + c_l * WSTR + ch * 128;
#pragma unroll 8
            for (int k4 = 0; k4 < 32; k4++) {
                const float4 ha = *reinterpret_cast<const float4*>(hs + r0 * HSTR + k4 * 4);
                const float4 hb = *reinterpret_cast<const float4*>(hs + r1 * HSTR + k4 * 4);
                const float4 w0 = *reinterpret_cast<const float4*>(w0r + k4 * 4);
                const float4 wx = *reinterpret_cast<const float4*>(wxr + k4 * 4);
                fma4(a00, ha, w0);
                fma4(a01, hb, w0);
                fma4(a10, ha, wx);
                fma4(a11, hb, wx);
            }
            __syncthreads();
        }

#pragma unroll 1
        for (int ch = 0; ch < 4; ch++) {
#pragma unroll
            for (int j = 0; j < 4; j++) {
                const int idx = tid + j * 256;
                const int rr = idx >> 5, cc = idx & 31;
                float4 v = __ldcg(reinterpret_cast<const float4*>(
                    h1prev + (long long)(bg * 32 + rr) * HH + ch * 128 + cc * 4));
                *reinterpret_cast<float4*>(hs + rr * HSTR + cc * 4) = v;
            }
            __syncthreads();
            const float* wlr = sm + OFF_WL + c_l * WSTR + ch * 128;
#pragma unroll 8
            for (int k4 = 0; k4 < 32; k4++) {
                const float4 ha = *reinterpret_cast<const float4*>(hs + r0 * HSTR + k4 * 4);
                const float4 hb = *reinterpret_cast<const float4*>(hs + r1 * HSTR + k4 * 4);
                const float4 wv = *reinterpret_cast<const float4*>(wlr + k4 * 4);
                fma4(a10, ha, wv);
                fma4(a11, hb, wv);
            }
            __syncthreads();
        }

        if (p < SS) {
            const int t0 = inputs[p * BB + gb0];
            const int t1 = inputs[p * BB + gb1];
            const float s0 = (a00.x + a00.y) + (a00.z + a00.w);
            const float s1 = (a01.x + a01.y) + (a01.z + a01.w);
            h0new[gb0 * HH + col] = tanhf(s0 + g_P[t0 * HH + col] + b0c);
            h0new[gb1 * HH + col] = tanhf(s1 + g_P[t1 * HH + col] + b0c);
        }
        if (p >= 1) {
            const int s = p - 1;
            const float s0 = (a10.x + a10.y) + (a10.z + a10.w);
            const float s1 = (a11.x + a11.y) + (a11.z + a11.w);
            const float v0 = tanhf(s0 + blc);
            const float v1 = tanhf(s1 + blc);
            h1new[gb0 * HH + col] = v0;
            h1new[gb1 * HH + col] = v1;
            const long long o0 = ((long long)s * BB + gb0) * HH + col;
            const long long o1 = ((long long)s * BB + gb1) * HH + col;
            __nv_bfloat16 hv0 = __float2bfloat16(v0);
            __nv_bfloat16 hv1 = __float2bfloat16(v1);
            g_Thi[o0] = hv0; g_Tlo[o0] = __float2bfloat16(v0 - __bfloat162float(hv0));
            g_Thi[o1] = hv1; g_Tlo[o1] = __float2bfloat16(v1 - __bfloat162float(hv1));
        }

        if (p < SS) grid_bar((unsigned)(p + 1) * RNN_CTAS);
    }
}

// ---------------- prep kernels -----------------------------------------------
__global__ void prep_w0x(const float* __restrict__ W0) {
    int idx = blockIdx.x * blockDim.x + threadIdx.x;
    if (idx >= HH * EE) return;
    int c = idx / EE;
    int e = idx % EE;
    float v = W0[c * (HH + EE) + HH + e];
    __nv_bfloat16 hi = __float2bfloat16(v);
    g_Xhi[c * EE + e] = hi;
    g_Xlo[c * EE + e] = __float2bfloat16(v - __bfloat162float(hi));
}

__global__ void split_arr(const float* __restrict__ src, __nv_bfloat16* __restrict__ hi,
                          __nv_bfloat16* __restrict__ lo, int n, float scale) {
    int i = blockIdx.x * blockDim.x + threadIdx.x;
    if (i >= n) return;
    float v = src[i] * scale;
    __nv_bfloat16 h = __float2bfloat16(v);
    hi[i] = h;
    lo[i] = __float2bfloat16(v - __bfloat162float(h));
}

__global__ void init_state(const float* __restrict__ hidden) {
    int i = blockIdx.x * blockDim.x + threadIdx.x;
    if (i == 0) g_sync = 0;
    if (i < BB * HH) {
        g_h0[1][i] = hidden[i];
        g_h1[1][i] = hidden[BB * HH + i];
    }
}

__global__ void write_hfinal(float* __restrict__ out) {
    int i = blockIdx.x * blockDim.x + threadIdx.x;
    if (i < BB * HH) {
        out[i] = g_h0[1][i];
        out[BB * HH + i] = g_h1[1][i];
    }
}

// ---------------- launch ------------------------------------------------------
extern "C" void kernel_launch(void* const* d_in, const int* in_sizes, int n_in,
                              void* d_out, int out_size) {
    const int*   inputs = (const int*)  d_in[0];
    const float* hidden = (const float*)d_in[1];
    const float* emb    = (const float*)d_in[2];
    const float* W0     = (const float*)d_in[3];
    const float* b0     = (const float*)d_in[4];
    const float* Wl     = (const float*)d_in[5];
    const float* bl     = (const float*)d_in[6];
    const float* Wout   = (const float*)d_in[7];
    const float* bout   = (const float*)d_in[8];

    float* logits = (float*)d_out;
    float* hfin   = (float*)d_out + (long long)SS * BB * VV;

    cudaFuncSetAttribute(gemm_hmma, cudaFuncAttributeMaxDynamicSharedMemorySize,
                         GEMM_SMEM);
    cudaFuncSetAttribute(rnn_persist, cudaFuncAttributeMaxDynamicSharedMemorySize,
                         RNN_SMEM);

    float* pP = nullptr;
    cudaGetSymbolAddress((void**)&pP, g_P);
    __nv_bfloat16 *pThi, *pTlo, *pWhi, *pWlo, *pEhi, *pElo, *pXhi, *pXlo;
    cudaGetSymbolAddress((void**)&pThi, g_Thi);
    cudaGetSymbolAddress((void**)&pTlo, g_Tlo);
    cudaGetSymbolAddress((void**)&pWhi, g_Whi);
    cudaGetSymbolAddress((void**)&pWlo, g_Wlo);
    cudaGetSymbolAddress((void**)&pEhi, g_Ehi);
    cudaGetSymbolAddress((void**)&pElo, g_Elo);
    cudaGetSymbolAddress((void**)&pXhi, g_Xhi);
    cudaGetSymbolAddress((void**)&pXlo, g_Xlo);

    const float scale = 22.62741699796952f;  // sqrt(512)

    // second stream for overlapped logits GEMM chunks (created per call; the
    // graph only records the launches/dependencies, not the stream objects)
    cudaStream_t s1;
    cudaStreamCreate(&s1);

    // 1. prep (default stream)
    init_state<<<(BB * HH + 255) / 256, 256>>>(hidden);
    prep_w0x<<<(HH * EE + 255) / 256, 256>>>(W0);
    split_arr<<<(VV * EE + 255) / 256, 256>>>(emb, pEhi, pElo, VV * EE, scale);
    split_arr<<<(VV * HH + 255) / 256, 256>>>(Wout, pWhi, pWlo, VV * HH, 1.0f);

    // fork point: s1 may start once Wout split is done
    cudaEvent_t evFork;
    cudaEventCreateWithFlags(&evFork, cudaEventDisableTiming);
    cudaEventRecord(evFork, 0);
    cudaStreamWaitEvent(s1, evFork, 0);

    // 2. P = scale*emb @ W0x^T (default stream; rnn needs it)
    {
        dim3 grid((HH + 127) / 128, (VV + 127) / 128);
        gemm_hmma<<<grid, 256, GEMM_SMEM>>>(pEhi, pElo, pXhi, pXlo,
                                            VV, HH, pP, HH, nullptr);
    }

    // 3+4. recurrence in 8 chunks; after chunk i, its 16 steps of tops are
    // final -> launch that logits slab on s1, overlapping with chunk i+1.
    static const int PH[9] = {0, 17, 33, 49, 65, 81, 97, 113, 129};
    cudaEvent_t evDone = nullptr;
    for (int i = 0; i < 8; i++) {
        rnn_persist<<<RNN_CTAS, RNN_THR, RNN_SMEM>>>(PH[i], PH[i + 1],
                                                     inputs, W0, b0, Wl, bl);
        cudaEvent_t ev;
        cudaEventCreateWithFlags(&ev, cudaEventDisableTiming);
        cudaEventRecord(ev, 0);
        cudaStreamWaitEvent(s1, ev, 0);

        const long long rowoff = (long long)2048 * i;
        dim3 grid((VV + 127) / 128, 16);   // 2048 rows per chunk
        gemm_hmma<<<grid, 256, GEMM_SMEM, s1>>>(
            pThi + rowoff * HH, pTlo + rowoff * HH, pWhi, pWlo,
            2048, VV, logits + rowoff * VV, VV, bout);

        if (i == 7) {
            cudaEventCreateWithFlags(&evDone, cudaEventDisableTiming);
            cudaEventRecord(evDone, s1);
        }
    }

    // join: default stream waits for the last logits chunk
    cudaStreamWaitEvent(0, evDone, 0);

    // 5. final hidden state
    write_hfinal<<<(BB * HH + 255) / 256, 256>>>(hfin);
}

// round 7
// speedup vs baseline: 1.2054x; 1.2054x over previous
#include <cuda_runtime.h>
#include <cuda_bf16.h>
#include <math.h>
#include <stdint.h>

#define SS 128
#define BB 128
#define VV 10000
#define HH 512
#define EE 512
#define KDIM 512

// ---------------- scratch (device globals: no allocations allowed) ----------
__device__ float g_P[VV * HH];         // scale * emb @ W0_x^T
__device__ float g_h0[2][BB * HH];     // ping-pong layer-0 hidden
__device__ float g_h1[2][BB * HH];     // ping-pong layer-1 hidden
__device__ unsigned int g_sync;        // grid barrier counter
// bf16 hi/lo split operands for tensor GEMMs
__device__ __nv_bfloat16 g_Thi[SS * BB * HH];
__device__ __nv_bfloat16 g_Tlo[SS * BB * HH];
__device__ __nv_bfloat16 g_Whi[VV * HH];
__device__ __nv_bfloat16 g_Wlo[VV * HH];
__device__ __nv_bfloat16 g_Ehi[VV * EE];
__device__ __nv_bfloat16 g_Elo[VV * EE];
__device__ __nv_bfloat16 g_Xhi[HH * EE];
__device__ __nv_bfloat16 g_Xlo[HH * EE];

// ============================ helpers ========================================
__device__ __forceinline__ uint32_t smem_u32(const void* p) {
    uint32_t a;
    asm("{ .reg .u64 t; cvta.to.shared.u64 t, %1; cvt.u32.u64 %0, t; }"
        : "=r"(a) : "l"(p));
    return a;
}

__device__ __forceinline__ void ldm_x4(uint32_t addr, uint32_t r[4]) {
    asm volatile("ldmatrix.sync.aligned.m8n8.x4.shared.b16 {%0,%1,%2,%3}, [%4];"
                 : "=r"(r[0]), "=r"(r[1]), "=r"(r[2]), "=r"(r[3]) : "r"(addr));
}

__device__ __forceinline__ void mma_bf16(float c[4], const uint32_t a[4],
                                         uint32_t b0, uint32_t b1) {
    asm volatile(
        "mma.sync.aligned.m16n8k16.row.col.f32.bf16.bf16.f32 "
        "{%0,%1,%2,%3}, {%4,%5,%6,%7}, {%8,%9}, {%0,%1,%2,%3};"
        : "+f"(c[0]), "+f"(c[1]), "+f"(c[2]), "+f"(c[3])
        : "r"(a[0]), "r"(a[1]), "r"(a[2]), "r"(a[3]), "r"(b0), "r"(b1));
}

__device__ __forceinline__ void fma4(float4& acc, const float4& a, const float4& b) {
    acc.x = fmaf(a.x, b.x, acc.x);
    acc.y = fmaf(a.y, b.y, acc.y);
    acc.z = fmaf(a.z, b.z, acc.z);
    acc.w = fmaf(a.w, b.w, acc.w);
}

// =================== bf16-split HMMA GEMM (unchanged, passing) ===============
#define BK 32
#define ROWB 80
#define TILE_SB (128 * ROWB)
#define STAGE_SB (4 * TILE_SB)
#define GEMM_SMEM (2 * STAGE_SB)
#define KT_N (KDIM / BK)

__global__ __launch_bounds__(256, 1)
void gemm_hmma(const __nv_bfloat16* __restrict__ Ahi,
               const __nv_bfloat16* __restrict__ Alo,
               const __nv_bfloat16* __restrict__ Bhi,
               const __nv_bfloat16* __restrict__ Blo,
               int M, int N, float* __restrict__ C, int ldc,
               const float* __restrict__ bias) {
    extern __shared__ char smem[];
    const uint32_t sb = smem_u32(smem);
    const int tid = threadIdx.x;
    const int wid = tid >> 5, lid = tid & 31;
    const int wm = wid & 3, wn = wid >> 2;
    const int nb = blockIdx.x, mb = blockIdx.y;

    const __nv_bfloat16* __restrict__ srcs[4] = {Ahi, Alo, Bhi, Blo};

    float acc[2][8][4];
#pragma unroll
    for (int i = 0; i < 2; i++)
#pragma unroll
        for (int j = 0; j < 8; j++)
#pragma unroll
            for (int q = 0; q < 4; q++) acc[i][j][q] = 0.0f;

    auto load_stage = [&](int st, int kt) {
#pragma unroll
        for (int t = 0; t < 4; t++) {
#pragma unroll
            for (int i = 0; i < 2; i++) {
                const int idx = tid + i * 256;
                const int row = idx >> 2, ch = idx & 3;
                const long long grow =
                    (t < 2) ? (long long)mb * 128 + row : (long long)nb * 128 + row;
                const bool ok = (t < 2) ? (grow < M) : (grow < N);
                const __nv_bfloat16* src = srcs[t] + grow * KDIM + kt * BK + ch * 8;
                const uint32_t dst = sb + st * STAGE_SB + t * TILE_SB + row * ROWB + ch * 16;
                const int sz = ok ? 16 : 0;
                asm volatile("cp.async.cg.shared.global [%0], [%1], 16, %2;"
                             :: "r"(dst), "l"(src), "r"(sz) : "memory");
            }
        }
    };

    const int lr = lid & 15;
    const int lc = lid >> 4;

    load_stage(0, 0);
    asm volatile("cp.async.commit_group;" ::: "memory");

    for (int kt = 0; kt < KT_N; kt++) {
        const int st = kt & 1;
        if (kt + 1 < KT_N) {
            load_stage(st ^ 1, kt + 1);
            asm volatile("cp.async.commit_group;" ::: "memory");
            asm volatile("cp.async.wait_group 1;" ::: "memory");
        } else {
            asm volatile("cp.async.wait_group 0;" ::: "memory");
        }
        __syncthreads();

        const uint32_t stg = sb + st * STAGE_SB;
        const uint32_t aBaseHi = stg + 0 * TILE_SB;
        const uint32_t aBaseLo = stg + 1 * TILE_SB;
        const uint32_t bBaseHi = stg + 2 * TILE_SB;
        const uint32_t bBaseLo = stg + 3 * TILE_SB;

#pragma unroll
        for (int k16 = 0; k16 < 2; k16++) {
            const uint32_t koff = k16 * 32 + lc * 16;

            uint32_t ahi[2][4], alo[2][4];
#pragma unroll
            for (int mf = 0; mf < 2; mf++) {
                const uint32_t roff = (uint32_t)(wm * 32 + mf * 16 + lr) * ROWB + koff;
                ldm_x4(aBaseHi + roff, ahi[mf]);
                ldm_x4(aBaseLo + roff, alo[mf]);
            }
#pragma unroll
            for (int reg = 0; reg < 4; reg++) {
                const uint32_t roff = (uint32_t)(wn * 64 + reg * 16 + lr) * ROWB + koff;
                uint32_t bh[4], bl2[4];
                ldm_x4(bBaseHi + roff, bh);
                ldm_x4(bBaseLo + roff, bl2);
#pragma unroll
                for (int mf = 0; mf < 2; mf++) {
                    mma_bf16(acc[mf][reg * 2 + 0], ahi[mf], bh[0], bh[2]);
                    mma_bf16(acc[mf][reg * 2 + 0], ahi[mf], bl2[0], bl2[2]);
                    mma_bf16(acc[mf][reg * 2 + 0], alo[mf], bh[0], bh[2]);
                    mma_bf16(acc[mf][reg * 2 + 1], ahi[mf], bh[1], bh[3]);
                    mma_bf16(acc[mf][reg * 2 + 1], ahi[mf], bl2[1], bl2[3]);
                    mma_bf16(acc[mf][reg * 2 + 1], alo[mf], bh[1], bh[3]);
                }
            }
        }
        __syncthreads();
    }

    const int lr4 = lid >> 2;
    const int lc2 = (lid & 3) * 2;
#pragma unroll
    for (int mf = 0; mf < 2; mf++) {
#pragma unroll
        for (int nf = 0; nf < 8; nf++) {
            const int m = mb * 128 + wm * 32 + mf * 16 + lr4;
            const int n = nb * 128 + wn * 64 + nf * 8 + lc2;
            if (n >= N) continue;
            float b0 = 0.f, b1 = 0.f;
            if (bias) { b0 = bias[n]; b1 = bias[n + 1]; }
            if (m < M) {
                float2 v = make_float2(acc[mf][nf][0] + b0, acc[mf][nf][1] + b1);
                *reinterpret_cast<float2*>(C + (long long)m * ldc + n) = v;
            }
            if (m + 8 < M) {
                float2 v = make_float2(acc[mf][nf][2] + b0, acc[mf][nf][3] + b1);
                *reinterpret_cast<float2*>(C + (long long)(m + 8) * ldc + n) = v;
            }
        }
    }
}

// =================== persistent recurrence kernel v2 =========================
// 128 CTAs = 4 bg(32 rows) x 32 cg(16 cols). 256 threads =
//   64 spatial (8 rgrp x 8 cgrp; 4 rows x 2 cols per thread) x 4 k-slices.
// Weights smem-resident; h staged with cp.async (h1 prefetched during pass1);
// k-slice partials reduced via smem (aliased onto the h0 buffer).

#define RNN_CTAS 128
#define RNN_THR 256
#define WSTR 516
#define HSTR 516
#define OFF_W0 0
#define OFF_WL (16 * WSTR)                 // 8256
#define OFF_WX (32 * WSTR)                 // 16512
#define OFF_H0 (48 * WSTR)                 // 24768
#define OFF_H1 (OFF_H0 + 32 * HSTR)        // 41280
#define RNN_SMEM ((OFF_H1 + 32 * HSTR) * 4)  // 231168 B
#define OFF_RED OFF_H0                     // reduction aliases h0 buffer
// red float index: layer*2176 + ks*544 + row*17 + col

__device__ __forceinline__ void grid_bar(unsigned int target) {
    __syncthreads();
    if (threadIdx.x == 0) {
        unsigned int* p = &g_sync;
        asm volatile("red.release.gpu.global.add.u32 [%0], 1;" :: "l"(p) : "memory");
        unsigned int v;
        do {
            asm volatile("ld.acquire.gpu.global.u32 %0, [%1];" : "=r"(v) : "l"(p) : "memory");
        } while (v < target);
    }
    __syncthreads();
}

__global__ __launch_bounds__(RNN_THR, 1)
void rnn_persist(const int* __restrict__ inputs,
                 const float* __restrict__ W0,
                 const float* __restrict__ b0,
                 const float* __restrict__ Wl,
                 const float* __restrict__ bl) {
    extern __shared__ float sm[];
    const uint32_t sbase = smem_u32(sm);
    const int tid = threadIdx.x;
    const int bg = blockIdx.x >> 5;        // rows [bg*32, bg*32+32)
    const int cg = blockIdx.x & 31;        // cols [cg*16, cg*16+16)
    const int cbase = cg * 16;

    // ---- load weight slices into smem (once) ----
    for (int i = tid; i < 16 * 512; i += RNN_THR) {
        const int r = i >> 9, k = i & 511;
        const int gc = cbase + r;
        sm[OFF_W0 + r * WSTR + k] = W0[gc * 1024 + k];         // layer0 h-part
        sm[OFF_WL + r * WSTR + k] = Wl[gc * 1024 + k];         // layer1 h1-part
        sm[OFF_WX + r * WSTR + k] = Wl[gc * 1024 + 512 + k];   // layer1 h0-part
    }
    __syncthreads();

    // compute-thread mapping
    const int ks = tid >> 6;               // 0..3 k-slice
    const int sp = tid & 63;
    const int rgrp = sp >> 3;              // 0..7 -> rows rgrp*4..+3
    const int cgrp = sp & 7;               // 0..7 -> cols cgrp*2, +1
    const int kbase = ks * 128;            // float offset in k

    // epilogue-thread mapping (2 cells: rows er, er+16; same col)
    const int ecoll = tid & 15;
    const int erow = tid >> 4;             // 0..15
    const int ecol = cbase + ecoll;
    const float b0c = b0[ecol];
    const float blc = bl[ecol];

    for (int p = 0; p <= SS; p++) {
        const float* __restrict__ h0old = g_h0[(p + 1) & 1];
        const float* __restrict__ h1prev = g_h1[p & 1];
        float* __restrict__ h0new = g_h0[p & 1];
        float* __restrict__ h1new = g_h1[(p + 1) & 1];

        // ---- stage h0 (group A) and prefetch h1 (group B) via cp.async ----
#pragma unroll
        for (int j = 0; j < 16; j++) {
            const int idx = tid + j * 256;             // 4096 float4 tiles
            const int row = idx >> 7;
            const int c4 = (idx & 127) * 4;
            const uint32_t dst = sbase + (OFF_H0 + row * HSTR + c4) * 4;
            const float* src = h0old + (long long)(bg * 32 + row) * HH + c4;
            asm volatile("cp.async.cg.shared.global [%0], [%1], 16;"
                         :: "r"(dst), "l"(src) : "memory");
        }
        asm volatile("cp.async.commit_group;" ::: "memory");
#pragma unroll
        for (int j = 0; j < 16; j++) {
            const int idx = tid + j * 256;
            const int row = idx >> 7;
            const int c4 = (idx & 127) * 4;
            const uint32_t dst = sbase + (OFF_H1 + row * HSTR + c4) * 4;
            const float* src = h1prev + (long long)(bg * 32 + row) * HH + c4;
            asm volatile("cp.async.cg.shared.global [%0], [%1], 16;"
                         :: "r"(dst), "l"(src) : "memory");
        }
        asm volatile("cp.async.commit_group;" ::: "memory");
        asm volatile("cp.async.wait_group 1;" ::: "memory");   // h0 ready
        __syncthreads();

        float4 acc0[4][2], acc1[4][2];
#pragma unroll
        for (int r = 0; r < 4; r++)
#pragma unroll
            for (int j = 0; j < 2; j++) {
                acc0[r][j] = make_float4(0, 0, 0, 0);
                acc1[r][j] = make_float4(0, 0, 0, 0);
            }

        // ---- pass 1: h0old x (W0h -> acc0, Wlx -> acc1) ----
        {
            const float* h0p = sm + OFF_H0 + (rgrp * 4) * HSTR + kbase;
            const float* w0p = sm + OFF_W0 + (cgrp * 2) * WSTR + kbase;
            const float* wxp = sm + OFF_WX + (cgrp * 2) * WSTR + kbase;
#pragma unroll 4
            for (int i = 0; i < 32; i++) {
                float4 hv[4], w0v[2], wxv[2];
#pragma unroll
                for (int r = 0; r < 4; r++)
                    hv[r] = *reinterpret_cast<const float4*>(h0p + r * HSTR + i * 4);
#pragma unroll
                for (int j = 0; j < 2; j++) {
                    w0v[j] = *reinterpret_cast<const float4*>(w0p + j * WSTR + i * 4);
                    wxv[j] = *reinterpret_cast<const float4*>(wxp + j * WSTR + i * 4);
                }
#pragma unroll
                for (int r = 0; r < 4; r++)
#pragma unroll
                    for (int j = 0; j < 2; j++) {
                        fma4(acc0[r][j], hv[r], w0v[j]);
                        fma4(acc1[r][j], hv[r], wxv[j]);
                    }
            }
        }

        asm volatile("cp.async.wait_group 0;" ::: "memory");   // h1 ready
        __syncthreads();   // also: all pass1 smem reads done -> h0 buf reusable

        // ---- pass 2: h1prev x Wlh -> acc1 ----
        {
            const float* h1p = sm + OFF_H1 + (rgrp * 4) * HSTR + kbase;
            const float* wlp = sm + OFF_WL + (cgrp * 2) * WSTR + kbase;
#pragma unroll 4
            for (int i = 0; i < 32; i++) {
                float4 hv[4], wlv[2];
#pragma unroll
                for (int r = 0; r < 4; r++)
                    hv[r] = *reinterpret_cast<const float4*>(h1p + r * HSTR + i * 4);
#pragma unroll
                for (int j = 0; j < 2; j++)
                    wlv[j] = *reinterpret_cast<const float4*>(wlp + j * WSTR + i * 4);
#pragma unroll
                for (int r = 0; r < 4; r++)
#pragma unroll
                    for (int j = 0; j < 2; j++)
                        fma4(acc1[r][j], hv[r], wlv[j]);
            }
        }

        // ---- write k-slice partials into red (aliased on h0 buffer) ----
#pragma unroll
        for (int r = 0; r < 4; r++)
#pragma unroll
            for (int j = 0; j < 2; j++) {
                const int row = rgrp * 4 + r;
                const int coll = cgrp * 2 + j;
                const float s0 = (acc0[r][j].x + acc0[r][j].y) +
                                 (acc0[r][j].z + acc0[r][j].w);
                const float s1 = (acc1[r][j].x + acc1[r][j].y) +
                                 (acc1[r][j].z + acc1[r][j].w);
                sm[OFF_RED + 0 * 2176 + ks * 544 + row * 17 + coll] = s0;
                sm[OFF_RED + 1 * 2176 + ks * 544 + row * 17 + coll] = s1;
            }
        __syncthreads();

        // ---- epilogue: 2 cells per thread (rows erow, erow+16; col ecol) ----
#pragma unroll
        for (int e = 0; e < 2; e++) {
            const int row = erow + e * 16;
            const int gbr = bg * 32 + row;
            float sum0 = 0.f, sum1 = 0.f;
#pragma unroll
            for (int q = 0; q < 4; q++) {
                sum0 += sm[OFF_RED + 0 * 2176 + q * 544 + row * 17 + ecoll];
                sum1 += sm[OFF_RED + 1 * 2176 + q * 544 + row * 17 + ecoll];
            }
            if (p < SS) {
                const int tok = inputs[p * BB + gbr];
                h0new[gbr * HH + ecol] = tanhf(sum0 + g_P[tok * HH + ecol] + b0c);
            }
            if (p >= 1) {
                const int s = p - 1;
                const float v = tanhf(sum1 + blc);
                h1new[gbr * HH + ecol] = v;
                const long long o = ((long long)s * BB + gbr) * HH + ecol;
                const __nv_bfloat16 hv = __float2bfloat16(v);
                g_Thi[o] = hv;
                g_Tlo[o] = __float2bfloat16(v - __bfloat162float(hv));
            }
        }

        if (p < SS) grid_bar((unsigned)(p + 1) * RNN_CTAS);
    }
}

// ---------------- prep kernels -----------------------------------------------
__global__ void prep_w0x(const float* __restrict__ W0) {
    int idx = blockIdx.x * blockDim.x + threadIdx.x;
    if (idx >= HH * EE) return;
    int c = idx / EE;
    int e = idx % EE;
    float v = W0[c * (HH + EE) + HH + e];
    __nv_bfloat16 hi = __float2bfloat16(v);
    g_Xhi[c * EE + e] = hi;
    g_Xlo[c * EE + e] = __float2bfloat16(v - __bfloat162float(hi));
}

__global__ void split_arr(const float* __restrict__ src, __nv_bfloat16* __restrict__ hi,
                          __nv_bfloat16* __restrict__ lo, int n, float scale) {
    int i = blockIdx.x * blockDim.x + threadIdx.x;
    if (i >= n) return;
    float v = src[i] * scale;
    __nv_bfloat16 h = __float2bfloat16(v);
    hi[i] = h;
    lo[i] = __float2bfloat16(v - __bfloat162float(h));
}

__global__ void init_state(const float* __restrict__ hidden) {
    int i = blockIdx.x * blockDim.x + threadIdx.x;
    if (i == 0) g_sync = 0;
    if (i < BB * HH) {
        g_h0[1][i] = hidden[i];
        g_h1[1][i] = hidden[BB * HH + i];
    }
}

__global__ void write_hfinal(float* __restrict__ out) {
    int i = blockIdx.x * blockDim.x + threadIdx.x;
    if (i < BB * HH) {
        out[i] = g_h0[1][i];
        out[BB * HH + i] = g_h1[1][i];
    }
}

// ---------------- launch ------------------------------------------------------
extern "C" void kernel_launch(void* const* d_in, const int* in_sizes, int n_in,
                              void* d_out, int out_size) {
    const int*   inputs = (const int*)  d_in[0];
    const float* hidden = (const float*)d_in[1];
    const float* emb    = (const float*)d_in[2];
    const float* W0     = (const float*)d_in[3];
    const float* b0     = (const float*)d_in[4];
    const float* Wl     = (const float*)d_in[5];
    const float* bl     = (const float*)d_in[6];
    const float* Wout   = (const float*)d_in[7];
    const float* bout   = (const float*)d_in[8];

    float* logits = (float*)d_out;
    float* hfin   = (float*)d_out + (long long)SS * BB * VV;

    cudaFuncSetAttribute(gemm_hmma, cudaFuncAttributeMaxDynamicSharedMemorySize,
                         GEMM_SMEM);
    cudaFuncSetAttribute(rnn_persist, cudaFuncAttributeMaxDynamicSharedMemorySize,
                         RNN_SMEM);

    float* pP = nullptr;
    cudaGetSymbolAddress((void**)&pP, g_P);
    __nv_bfloat16 *pThi, *pTlo, *pWhi, *pWlo, *pEhi, *pElo, *pXhi, *pXlo;
    cudaGetSymbolAddress((void**)&pThi, g_Thi);
    cudaGetSymbolAddress((void**)&pTlo, g_Tlo);
    cudaGetSymbolAddress((void**)&pWhi, g_Whi);
    cudaGetSymbolAddress((void**)&pWlo, g_Wlo);
    cudaGetSymbolAddress((void**)&pEhi, g_Ehi);
    cudaGetSymbolAddress((void**)&pElo, g_Elo);
    cudaGetSymbolAddress((void**)&pXhi, g_Xhi);
    cudaGetSymbolAddress((void**)&pXlo, g_Xlo);

    const float scale = 22.62741699796952f;  // sqrt(512)

    // 1. prep
    init_state<<<(BB * HH + 255) / 256, 256>>>(hidden);
    prep_w0x<<<(HH * EE + 255) / 256, 256>>>(W0);
    split_arr<<<(VV * EE + 255) / 256, 256>>>(emb, pEhi, pElo, VV * EE, scale);
    split_arr<<<(VV * HH + 255) / 256, 256>>>(Wout, pWhi, pWlo, VV * HH, 1.0f);

    // 2. P = scale*emb @ W0x^T  (M=10000, N=512, K=512)
    {
        dim3 grid((HH + 127) / 128, (VV + 127) / 128);
        gemm_hmma<<<grid, 256, GEMM_SMEM>>>(pEhi, pElo, pXhi, pXlo,
                                            VV, HH, pP, HH, nullptr);
    }

    // 3. full recurrence in ONE persistent kernel
    rnn_persist<<<RNN_CTAS, RNN_THR, RNN_SMEM>>>(inputs, W0, b0, Wl, bl);

    // 4. logits = tops @ Wout^T + bout  (M=16384, N=10000, K=512)
    {
        dim3 grid((VV + 127) / 128, (SS * BB + 127) / 128);
        gemm_hmma<<<grid, 256, GEMM_SMEM>>>(pThi, pTlo, pWhi, pWlo,
                                            SS * BB, VV, logits, VV, bout);
    }

    // 5. final hidden state
    write_hfinal<<<(BB * HH + 255) / 256, 256>>>(hfin);
}

// round 8
// speedup vs baseline: 1.5086x; 1.2515x over previous
#include <cuda_runtime.h>
#include <cuda_bf16.h>
#include <math.h>
#include <stdint.h>

#define SS 128
#define BB 128
#define VV 10000
#define HH 512
#define EE 512
#define KDIM 512

// ---------------- scratch (device globals: no allocations allowed) ----------
__device__ float g_P[VV * HH];          // scale * emb @ W0_x^T
__device__ unsigned int g_sync;         // grid barrier counter
// hidden state as bf16 hi/lo ping-pong (MMA operands)
__device__ __nv_bfloat16 g_h0bh[2][BB * HH], g_h0bl[2][BB * HH];
__device__ __nv_bfloat16 g_h1bh[2][BB * HH], g_h1bl[2][BB * HH];
__device__ float g_h0f[BB * HH], g_h1f[BB * HH];   // fp32 finals
// bf16 hi/lo split operands for tensor GEMMs
__device__ __nv_bfloat16 g_Thi[SS * BB * HH];
__device__ __nv_bfloat16 g_Tlo[SS * BB * HH];
__device__ __nv_bfloat16 g_Whi[VV * HH];
__device__ __nv_bfloat16 g_Wlo[VV * HH];
__device__ __nv_bfloat16 g_Ehi[VV * EE];
__device__ __nv_bfloat16 g_Elo[VV * EE];
__device__ __nv_bfloat16 g_Xhi[HH * EE];
__device__ __nv_bfloat16 g_Xlo[HH * EE];

// ============================ helpers ========================================
__device__ __forceinline__ uint32_t smem_u32(const void* p) {
    uint32_t a;
    asm("{ .reg .u64 t; cvta.to.shared.u64 t, %1; cvt.u32.u64 %0, t; }"
        : "=r"(a) : "l"(p));
    return a;
}

__device__ __forceinline__ void ldm_x4(uint32_t addr, uint32_t r[4]) {
    asm volatile("ldmatrix.sync.aligned.m8n8.x4.shared.b16 {%0,%1,%2,%3}, [%4];"
                 : "=r"(r[0]), "=r"(r[1]), "=r"(r[2]), "=r"(r[3]) : "r"(addr));
}

__device__ __forceinline__ void mma_bf16(float c[4], const uint32_t a[4],
                                         uint32_t b0, uint32_t b1) {
    asm volatile(
        "mma.sync.aligned.m16n8k16.row.col.f32.bf16.bf16.f32 "
        "{%0,%1,%2,%3}, {%4,%5,%6,%7}, {%8,%9}, {%0,%1,%2,%3};"
        : "+f"(c[0]), "+f"(c[1]), "+f"(c[2]), "+f"(c[3])
        : "r"(a[0]), "r"(a[1]), "r"(a[2]), "r"(a[3]), "r"(b0), "r"(b1));
}

// =================== bf16-split HMMA GEMM, 4-stage pipeline ==================
#define BK 32
#define ROWB 80
#define TILE_SB (128 * ROWB)
#define STAGE_SB (4 * TILE_SB)
#define NST 4
#define GEMM_SMEM (NST * STAGE_SB)     // 163840
#define KT_N (KDIM / BK)               // 16

__global__ __launch_bounds__(256, 1)
void gemm_hmma(const __nv_bfloat16* __restrict__ Ahi,
               const __nv_bfloat16* __restrict__ Alo,
               const __nv_bfloat16* __restrict__ Bhi,
               const __nv_bfloat16* __restrict__ Blo,
               int M, int N, float* __restrict__ C, int ldc,
               const float* __restrict__ bias) {
    extern __shared__ char smem[];
    const uint32_t sb = smem_u32(smem);
    const int tid = threadIdx.x;
    const int wid = tid >> 5, lid = tid & 31;
    const int wm = wid & 3, wn = wid >> 2;
    const int nb = blockIdx.x, mb = blockIdx.y;

    const __nv_bfloat16* __restrict__ srcs[4] = {Ahi, Alo, Bhi, Blo};

    float acc[2][8][4];
#pragma unroll
    for (int i = 0; i < 2; i++)
#pragma unroll
        for (int j = 0; j < 8; j++)
#pragma unroll
            for (int q = 0; q < 4; q++) acc[i][j][q] = 0.0f;

    auto load_stage = [&](int st, int kt) {
#pragma unroll
        for (int t = 0; t < 4; t++) {
#pragma unroll
            for (int i = 0; i < 2; i++) {
                const int idx = tid + i * 256;
                const int row = idx >> 2, ch = idx & 3;
                const long long grow =
                    (t < 2) ? (long long)mb * 128 + row : (long long)nb * 128 + row;
                const bool ok = (t < 2) ? (grow < M) : (grow < N);
                const __nv_bfloat16* src = srcs[t] + grow * KDIM + kt * BK + ch * 8;
                const uint32_t dst = sb + st * STAGE_SB + t * TILE_SB + row * ROWB + ch * 16;
                const int sz = ok ? 16 : 0;
                asm volatile("cp.async.cg.shared.global [%0], [%1], 16, %2;"
                             :: "r"(dst), "l"(src), "r"(sz) : "memory");
            }
        }
        asm volatile("cp.async.commit_group;" ::: "memory");
    };

    const int lr = lid & 15;
    const int lc = lid >> 4;

    load_stage(0, 0);
    load_stage(1, 1);
    load_stage(2, 2);

    for (int kt = 0; kt < KT_N; kt++) {
        if (kt < KT_N - 2)
            asm volatile("cp.async.wait_group 2;" ::: "memory");
        else if (kt == KT_N - 2)
            asm volatile("cp.async.wait_group 1;" ::: "memory");
        else
            asm volatile("cp.async.wait_group 0;" ::: "memory");
        __syncthreads();
        if (kt + 3 < KT_N) load_stage((kt + 3) & 3, kt + 3);

        const uint32_t stg = sb + (kt & 3) * STAGE_SB;
        const uint32_t aBaseHi = stg + 0 * TILE_SB;
        const uint32_t aBaseLo = stg + 1 * TILE_SB;
        const uint32_t bBaseHi = stg + 2 * TILE_SB;
        const uint32_t bBaseLo = stg + 3 * TILE_SB;

#pragma unroll
        for (int k16 = 0; k16 < 2; k16++) {
            const uint32_t koff = k16 * 32 + lc * 16;

            uint32_t ahi[2][4], alo[2][4];
#pragma unroll
            for (int mf = 0; mf < 2; mf++) {
                const uint32_t roff = (uint32_t)(wm * 32 + mf * 16 + lr) * ROWB + koff;
                ldm_x4(aBaseHi + roff, ahi[mf]);
                ldm_x4(aBaseLo + roff, alo[mf]);
            }
#pragma unroll
            for (int reg = 0; reg < 4; reg++) {
                const uint32_t roff = (uint32_t)(wn * 64 + reg * 16 + lr) * ROWB + koff;
                uint32_t bh[4], bl2[4];
                ldm_x4(bBaseHi + roff, bh);
                ldm_x4(bBaseLo + roff, bl2);
#pragma unroll
                for (int mf = 0; mf < 2; mf++) {
                    mma_bf16(acc[mf][reg * 2 + 0], ahi[mf], bh[0], bh[2]);
                    mma_bf16(acc[mf][reg * 2 + 0], ahi[mf], bl2[0], bl2[2]);
                    mma_bf16(acc[mf][reg * 2 + 0], alo[mf], bh[0], bh[2]);
                    mma_bf16(acc[mf][reg * 2 + 1], ahi[mf], bh[1], bh[3]);
                    mma_bf16(acc[mf][reg * 2 + 1], ahi[mf], bl2[1], bl2[3]);
                    mma_bf16(acc[mf][reg * 2 + 1], alo[mf], bh[1], bh[3]);
                }
            }
        }
    }

    const int lr4 = lid >> 2;
    const int lc2 = (lid & 3) * 2;
#pragma unroll
    for (int mf = 0; mf < 2; mf++) {
#pragma unroll
        for (int nf = 0; nf < 8; nf++) {
            const int m = mb * 128 + wm * 32 + mf * 16 + lr4;
            const int n = nb * 128 + wn * 64 + nf * 8 + lc2;
            if (n >= N) continue;
            float b0 = 0.f, b1 = 0.f;
            if (bias) { b0 = bias[n]; b1 = bias[n + 1]; }
            if (m < M) {
                float2 v = make_float2(acc[mf][nf][0] + b0, acc[mf][nf][1] + b1);
                *reinterpret_cast<float2*>(C + (long long)m * ldc + n) = v;
            }
            if (m + 8 < M) {
                float2 v = make_float2(acc[mf][nf][2] + b0, acc[mf][nf][3] + b1);
                *reinterpret_cast<float2*>(C + (long long)(m + 8) * ldc + n) = v;
            }
        }
    }
}

// =================== persistent recurrence kernel v3 (tensor cores) =========
// 128 CTAs = 4 bg(32 batch rows) x 32 cg(16 out cols). 256 threads = 8 warps
// (2 m-frags x 4 k-slices). Weights bf16 hi/lo smem-resident as [n16][k512]
// ldmatrix tiles. h state global bf16 hi/lo ping-pong, staged via cp.async.
// Phase p: acc0 = W0h . h0(p-1)  [layer0];  acc1 = Wlx . h0(p-1) + Wlh . h1(p-2).

#define RNN_CTAS 128
#define RNN_THR 256
#define WT_STRIDE 1040                    // bytes per tile row (1024 + 16 pad)
#define WT_TILE (16 * WT_STRIDE)          // 16640
#define HT_TILE (32 * WT_STRIDE)          // 33280
#define OFF_W 0                           // 6 weight tiles (W0h,Wlx,Wlh x hi/lo)
#define OFF_H (6 * WT_TILE)               // 99840: h hi tile, then lo tile
#define OFF_R (OFF_H + 2 * HT_TILE)       // 166400: reduction, fp32
#define REDSTR 17
#define RNN_SMEM (OFF_R + 2 * 4 * 32 * REDSTR * 4)   // 183808

__device__ __forceinline__ void grid_bar(unsigned int target) {
    __syncthreads();
    if (threadIdx.x == 0) {
        unsigned int* p = &g_sync;
        asm volatile("red.release.gpu.global.add.u32 [%0], 1;" :: "l"(p) : "memory");
        unsigned int v;
        do {
            asm volatile("ld.acquire.gpu.global.u32 %0, [%1];" : "=r"(v) : "l"(p) : "memory");
        } while (v < target);
    }
    __syncthreads();
}

__global__ __launch_bounds__(RNN_THR, 1)
void rnn_persist(const int* __restrict__ inputs,
                 const float* __restrict__ W0,
                 const float* __restrict__ b0,
                 const float* __restrict__ Wl,
                 const float* __restrict__ bl) {
    extern __shared__ char smc[];
    const uint32_t sbase = smem_u32(smc);
    float* const smf = reinterpret_cast<float*>(smc);
    const int tid = threadIdx.x;
    const int wid = tid >> 5, lid = tid & 31;
    const int bg = blockIdx.x >> 5;
    const int cg = blockIdx.x & 31;
    const int cbase = cg * 16;

    // ---- split weight slices into smem bf16 hi/lo tiles (once) ----
    for (int i = tid; i < 16 * 512; i += RNN_THR) {
        const int r = i >> 9, k = i & 511;
        const int gc = cbase + r;
        float v[3];
        v[0] = W0[gc * 1024 + k];         // W0h (x h0)
        v[1] = Wl[gc * 1024 + 512 + k];   // Wlx (x h0)
        v[2] = Wl[gc * 1024 + k];         // Wlh (x h1)
#pragma unroll
        for (int t = 0; t < 3; t++) {
            const __nv_bfloat16 hi = __float2bfloat16(v[t]);
            const __nv_bfloat16 lo = __float2bfloat16(v[t] - __bfloat162float(hi));
            char* base = smc + OFF_W + (2 * t) * WT_TILE + r * WT_STRIDE + k * 2;
            *reinterpret_cast<__nv_bfloat16*>(base) = hi;
            *reinterpret_cast<__nv_bfloat16*>(base + WT_TILE) = lo;
        }
    }
    __syncthreads();

    const int mw = wid & 1;               // m-frag: rows mw*16..+15
    const int kw = wid >> 1;              // k-slice: [kw*128, kw*128+128)
    const int lr = lid & 15, lc = lid >> 4;

    const int ecoll = tid & 15, erow = tid >> 4;
    const int ecol = cbase + ecoll;
    const float b0c = b0[ecol], blc = bl[ecol];

    const uint32_t abase = sbase + OFF_H + (mw * 16 + lr) * WT_STRIDE + lc * 16;
    const uint32_t bbase = sbase + OFF_W + lr * WT_STRIDE + lc * 16;

    for (int p = 0; p <= SS; p++) {
        float acc0[2][4] = {{0, 0, 0, 0}, {0, 0, 0, 0}};
        float acc1[2][4] = {{0, 0, 0, 0}, {0, 0, 0, 0}};

        // ---- stage h0(p-1) hi/lo ----
        {
            const __nv_bfloat16* hi = g_h0bh[(p + 1) & 1];
            const __nv_bfloat16* lo = g_h0bl[(p + 1) & 1];
#pragma unroll
            for (int j = 0; j < 16; j++) {
                const int idx = tid + j * 256;
                const int tile = idx >> 11;
                const int c = idx & 2047, row = c >> 6, ch = c & 63;
                const __nv_bfloat16* src =
                    (tile ? lo : hi) + (long long)(bg * 32 + row) * HH + ch * 8;
                const uint32_t dst = sbase + OFF_H + tile * HT_TILE + row * WT_STRIDE + ch * 16;
                asm volatile("cp.async.cg.shared.global [%0], [%1], 16;"
                             :: "r"(dst), "l"(src) : "memory");
            }
            asm volatile("cp.async.commit_group;" ::: "memory");
            asm volatile("cp.async.wait_group 0;" ::: "memory");
        }
        __syncthreads();

        // ---- pass A: h0 x W0h -> acc0 ; h0 x Wlx -> acc1 ----
#pragma unroll
        for (int i = 0; i < 8; i++) {
            const uint32_t koff = (uint32_t)(kw * 128 + i * 16) * 2;
            uint32_t ah[4], al[4], b0h[4], b0l[4], bxh[4], bxl[4];
            ldm_x4(abase + koff, ah);
            ldm_x4(abase + HT_TILE + koff, al);
            ldm_x4(bbase + 0 * WT_TILE + koff, b0h);
            ldm_x4(bbase + 1 * WT_TILE + koff, b0l);
            ldm_x4(bbase + 2 * WT_TILE + koff, bxh);
            ldm_x4(bbase + 3 * WT_TILE + koff, bxl);
            mma_bf16(acc0[0], ah, b0h[0], b0h[2]);
            mma_bf16(acc0[1], ah, b0h[1], b0h[3]);
            mma_bf16(acc0[0], ah, b0l[0], b0l[2]);
            mma_bf16(acc0[1], ah, b0l[1], b0l[3]);
            mma_bf16(acc0[0], al, b0h[0], b0h[2]);
            mma_bf16(acc0[1], al, b0h[1], b0h[3]);
            mma_bf16(acc1[0], ah, bxh[0], bxh[2]);
            mma_bf16(acc1[1], ah, bxh[1], bxh[3]);
            mma_bf16(acc1[0], ah, bxl[0], bxl[2]);
            mma_bf16(acc1[1], ah, bxl[1], bxl[3]);
            mma_bf16(acc1[0], al, bxh[0], bxh[2]);
            mma_bf16(acc1[1], al, bxh[1], bxh[3]);
        }
        __syncthreads();   // h tiles free for h1

        // ---- stage h1(p-2) hi/lo ----
        {
            const __nv_bfloat16* hi = g_h1bh[p & 1];
            const __nv_bfloat16* lo = g_h1bl[p & 1];
#pragma unroll
            for (int j = 0; j < 16; j++) {
                const int idx = tid + j * 256;
                const int tile = idx >> 11;
                const int c = idx & 2047, row = c >> 6, ch = c & 63;
                const __nv_bfloat16* src =
                    (tile ? lo : hi) + (long long)(bg * 32 + row) * HH + ch * 8;
                const uint32_t dst = sbase + OFF_H + tile * HT_TILE + row * WT_STRIDE + ch * 16;
                asm volatile("cp.async.cg.shared.global [%0], [%1], 16;"
                             :: "r"(dst), "l"(src) : "memory");
            }
            asm volatile("cp.async.commit_group;" ::: "memory");
            asm volatile("cp.async.wait_group 0;" ::: "memory");
        }
        __syncthreads();

        // ---- pass B: h1 x Wlh -> acc1 ----
#pragma unroll
        for (int i = 0; i < 8; i++) {
            const uint32_t koff = (uint32_t)(kw * 128 + i * 16) * 2;
            uint32_t ah[4], al[4], bhh[4], bhl[4];
            ldm_x4(abase + koff, ah);
            ldm_x4(abase + HT_TILE + koff, al);
            ldm_x4(bbase + 4 * WT_TILE + koff, bhh);
            ldm_x4(bbase + 5 * WT_TILE + koff, bhl);
            mma_bf16(acc1[0], ah, bhh[0], bhh[2]);
            mma_bf16(acc1[1], ah, bhh[1], bhh[3]);
            mma_bf16(acc1[0], ah, bhl[0], bhl[2]);
            mma_bf16(acc1[1], ah, bhl[1], bhl[3]);
            mma_bf16(acc1[0], al, bhh[0], bhh[2]);
            mma_bf16(acc1[1], al, bhh[1], bhh[3]);
        }

        // ---- write k-slice frags to red ----
        {
            const int rg = lid >> 2, cc = (lid & 3) * 2;
            float* red = smf + OFF_R / 4;
            const int m = mw * 16 + rg;
#pragma unroll
            for (int nf = 0; nf < 2; nf++) {
                const int n = nf * 8 + cc;
                float* r0 = red + ((0 * 4 + kw) * 32 + m) * REDSTR + n;
                float* r1 = red + ((1 * 4 + kw) * 32 + m) * REDSTR + n;
                r0[0] = acc0[nf][0]; r0[1] = acc0[nf][1];
                r0[8 * REDSTR] = acc0[nf][2]; r0[8 * REDSTR + 1] = acc0[nf][3];
                r1[0] = acc1[nf][0]; r1[1] = acc1[nf][1];
                r1[8 * REDSTR] = acc1[nf][2]; r1[8 * REDSTR + 1] = acc1[nf][3];
            }
        }
        __syncthreads();

        // ---- epilogue: reduce 4 k-slices, tanh, emit hi/lo ----
        {
            float* red = smf + OFF_R / 4;
#pragma unroll
            for (int e = 0; e < 2; e++) {
                const int row = erow + e * 16;
                const int gbr = bg * 32 + row;
                float s0 = 0.f, s1 = 0.f;
#pragma unroll
                for (int q = 0; q < 4; q++) {
                    s0 += red[((0 * 4 + q) * 32 + row) * REDSTR + ecoll];
                    s1 += red[((1 * 4 + q) * 32 + row) * REDSTR + ecoll];
                }
                const long long o = (long long)gbr * HH + ecol;
                if (p < SS) {
                    const int tok = inputs[p * BB + gbr];
                    const float v = tanhf(s0 + g_P[tok * HH + ecol] + b0c);
                    const __nv_bfloat16 hv = __float2bfloat16(v);
                    const __nv_bfloat16 lv = __float2bfloat16(v - __bfloat162float(hv));
                    g_h0bh[p & 1][o] = hv;
                    g_h0bl[p & 1][o] = lv;
                    if (p == SS - 1) g_h0f[o] = v;
                }
                if (p >= 1) {
                    const int s = p - 1;
                    const float v = tanhf(s1 + blc);
                    const __nv_bfloat16 hv = __float2bfloat16(v);
                    const __nv_bfloat16 lv = __float2bfloat16(v - __bfloat162float(hv));
                    g_h1bh[(p + 1) & 1][o] = hv;
                    g_h1bl[(p + 1) & 1][o] = lv;
                    const long long ot = ((long long)s * BB + gbr) * HH + ecol;
                    g_Thi[ot] = hv;
                    g_Tlo[ot] = lv;
                    if (p == SS) g_h1f[o] = v;
                }
            }
        }

        if (p < SS) grid_bar((unsigned)(p + 1) * RNN_CTAS);
    }
}

// ---------------- prep kernels -----------------------------------------------
__global__ void prep_w0x(const float* __restrict__ W0) {
    int idx = blockIdx.x * blockDim.x + threadIdx.x;
    if (idx >= HH * EE) return;
    int c = idx / EE;
    int e = idx % EE;
    float v = W0[c * (HH + EE) + HH + e];
    __nv_bfloat16 hi = __float2bfloat16(v);
    g_Xhi[c * EE + e] = hi;
    g_Xlo[c * EE + e] = __float2bfloat16(v - __bfloat162float(hi));
}

__global__ void split_arr(const float* __restrict__ src, __nv_bfloat16* __restrict__ hi,
                          __nv_bfloat16* __restrict__ lo, int n, float scale) {
    int i = blockIdx.x * blockDim.x + threadIdx.x;
    if (i >= n) return;
    float v = src[i] * scale;
    __nv_bfloat16 h = __float2bfloat16(v);
    hi[i] = h;
    lo[i] = __float2bfloat16(v - __bfloat162float(h));
}

__global__ void init_state(const float* __restrict__ hidden) {
    int i = blockIdx.x * blockDim.x + threadIdx.x;
    if (i == 0) g_sync = 0;
    if (i < BB * HH) {
        float v0 = hidden[i];
        __nv_bfloat16 h0 = __float2bfloat16(v0);
        g_h0bh[1][i] = h0;
        g_h0bl[1][i] = __float2bfloat16(v0 - __bfloat162float(h0));
        float v1 = hidden[BB * HH + i];
        __nv_bfloat16 h1 = __float2bfloat16(v1);
        g_h1bh[1][i] = h1;
        g_h1bl[1][i] = __float2bfloat16(v1 - __bfloat162float(h1));
    }
}

__global__ void write_hfinal(float* __restrict__ out) {
    int i = blockIdx.x * blockDim.x + threadIdx.x;
    if (i < BB * HH) {
        out[i] = g_h0f[i];
        out[BB * HH + i] = g_h1f[i];
    }
}

// ---------------- launch ------------------------------------------------------
extern "C" void kernel_launch(void* const* d_in, const int* in_sizes, int n_in,
                              void* d_out, int out_size) {
    const int*   inputs = (const int*)  d_in[0];
    const float* hidden = (const float*)d_in[1];
    const float* emb    = (const float*)d_in[2];
    const float* W0     = (const float*)d_in[3];
    const float* b0     = (const float*)d_in[4];
    const float* Wl     = (const float*)d_in[5];
    const float* bl     = (const float*)d_in[6];
    const float* Wout   = (const float*)d_in[7];
    const float* bout   = (const float*)d_in[8];

    float* logits = (float*)d_out;
    float* hfin   = (float*)d_out + (long long)SS * BB * VV;

    cudaFuncSetAttribute(gemm_hmma, cudaFuncAttributeMaxDynamicSharedMemorySize,
                         GEMM_SMEM);
    cudaFuncSetAttribute(rnn_persist, cudaFuncAttributeMaxDynamicSharedMemorySize,
                         RNN_SMEM);

    float* pP = nullptr;
    cudaGetSymbolAddress((void**)&pP, g_P);
    __nv_bfloat16 *pThi, *pTlo, *pWhi, *pWlo, *pEhi, *pElo, *pXhi, *pXlo;
    cudaGetSymbolAddress((void**)&pThi, g_Thi);
    cudaGetSymbolAddress((void**)&pTlo, g_Tlo);
    cudaGetSymbolAddress((void**)&pWhi, g_Whi);
    cudaGetSymbolAddress((void**)&pWlo, g_Wlo);
    cudaGetSymbolAddress((void**)&pEhi, g_Ehi);
    cudaGetSymbolAddress((void**)&pElo, g_Elo);
    cudaGetSymbolAddress((void**)&pXhi, g_Xhi);
    cudaGetSymbolAddress((void**)&pXlo, g_Xlo);

    const float scale = 22.62741699796952f;  // sqrt(512)

    // 1. prep
    init_state<<<(BB * HH + 255) / 256, 256>>>(hidden);
    prep_w0x<<<(HH * EE + 255) / 256, 256>>>(W0);
    split_arr<<<(VV * EE + 255) / 256, 256>>>(emb, pEhi, pElo, VV * EE, scale);
    split_arr<<<(VV * HH + 255) / 256, 256>>>(Wout, pWhi, pWlo, VV * HH, 1.0f);

    // 2. P = scale*emb @ W0x^T  (M=10000, N=512, K=512)
    {
        dim3 grid((HH + 127) / 128, (VV + 127) / 128);
        gemm_hmma<<<grid, 256, GEMM_SMEM>>>(pEhi, pElo, pXhi, pXlo,
                                            VV, HH, pP, HH, nullptr);
    }

    // 3. full recurrence in ONE persistent kernel (tensor cores)
    rnn_persist<<<RNN_CTAS, RNN_THR, RNN_SMEM>>>(inputs, W0, b0, Wl, bl);

    // 4. logits = tops @ Wout^T + bout  (M=16384, N=10000, K=512)
    {
        dim3 grid((VV + 127) / 128, (SS * BB + 127) / 128);
        gemm_hmma<<<grid, 256, GEMM_SMEM>>>(pThi, pTlo, pWhi, pWlo,
                                            SS * BB, VV, logits, VV, bout);
    }

    // 5. final hidden state
    write_hfinal<<<(BB * HH + 255) / 256, 256>>>(hfin);
}

// round 9
// speedup vs baseline: 1.6229x; 1.0757x over previous
#include <cuda_runtime.h>
#include <cuda_bf16.h>
#include <math.h>
#include <stdint.h>

#define SS 128
#define BB 128
#define VV 10000
#define HH 512
#define EE 512
#define KDIM 512

// ---------------- scratch (device globals: no allocations allowed) ----------
__device__ float g_P[VV * HH];          // scale * emb @ W0_x^T
__device__ unsigned int g_sync;         // grid barrier counter
// hidden state as bf16 hi/lo ping-pong (MMA operands)
__device__ __nv_bfloat16 g_h0bh[2][BB * HH], g_h0bl[2][BB * HH];
__device__ __nv_bfloat16 g_h1bh[2][BB * HH], g_h1bl[2][BB * HH];
__device__ float g_h0f[BB * HH], g_h1f[BB * HH];   // fp32 finals
// bf16 hi/lo split operands for tensor GEMMs
__device__ __nv_bfloat16 g_Thi[SS * BB * HH];
__device__ __nv_bfloat16 g_Tlo[SS * BB * HH];
__device__ __nv_bfloat16 g_Whi[VV * HH];
__device__ __nv_bfloat16 g_Wlo[VV * HH];
__device__ __nv_bfloat16 g_Ehi[VV * EE];
__device__ __nv_bfloat16 g_Elo[VV * EE];
__device__ __nv_bfloat16 g_Xhi[HH * EE];
__device__ __nv_bfloat16 g_Xlo[HH * EE];

// ============================ helpers ========================================
__device__ __forceinline__ uint32_t smem_u32(const void* p) {
    uint32_t a;
    asm("{ .reg .u64 t; cvta.to.shared.u64 t, %1; cvt.u32.u64 %0, t; }"
        : "=r"(a) : "l"(p));
    return a;
}

__device__ __forceinline__ void ldm_x4(uint32_t addr, uint32_t r[4]) {
    asm volatile("ldmatrix.sync.aligned.m8n8.x4.shared.b16 {%0,%1,%2,%3}, [%4];"
                 : "=r"(r[0]), "=r"(r[1]), "=r"(r[2]), "=r"(r[3]) : "r"(addr));
}

__device__ __forceinline__ void mma_bf16(float c[4], const uint32_t a[4],
                                         uint32_t b0, uint32_t b1) {
    asm volatile(
        "mma.sync.aligned.m16n8k16.row.col.f32.bf16.bf16.f32 "
        "{%0,%1,%2,%3}, {%4,%5,%6,%7}, {%8,%9}, {%0,%1,%2,%3};"
        : "+f"(c[0]), "+f"(c[1]), "+f"(c[2]), "+f"(c[3])
        : "r"(a[0]), "r"(a[1]), "r"(a[2]), "r"(a[3]), "r"(b0), "r"(b1));
}

// =================== bf16-split HMMA GEMM, 4-stage pipeline ==================
#define BK 32
#define ROWB 80
#define TILE_SB (128 * ROWB)
#define STAGE_SB (4 * TILE_SB)
#define NST 4
#define GEMM_SMEM (NST * STAGE_SB)     // 163840
#define KT_N (KDIM / BK)               // 16

__global__ __launch_bounds__(256, 1)
void gemm_hmma(const __nv_bfloat16* __restrict__ Ahi,
               const __nv_bfloat16* __restrict__ Alo,
               const __nv_bfloat16* __restrict__ Bhi,
               const __nv_bfloat16* __restrict__ Blo,
               int M, int N, float* __restrict__ C, int ldc,
               const float* __restrict__ bias) {
    extern __shared__ char smem[];
    const uint32_t sb = smem_u32(smem);
    const int tid = threadIdx.x;
    const int wid = tid >> 5, lid = tid & 31;
    const int wm = wid & 3, wn = wid >> 2;
    const int nb = blockIdx.x, mb = blockIdx.y;

    const __nv_bfloat16* __restrict__ srcs[4] = {Ahi, Alo, Bhi, Blo};

    float acc[2][8][4];
#pragma unroll
    for (int i = 0; i < 2; i++)
#pragma unroll
        for (int j = 0; j < 8; j++)
#pragma unroll
            for (int q = 0; q < 4; q++) acc[i][j][q] = 0.0f;

    auto load_stage = [&](int st, int kt) {
#pragma unroll
        for (int t = 0; t < 4; t++) {
#pragma unroll
            for (int i = 0; i < 2; i++) {
                const int idx = tid + i * 256;
                const int row = idx >> 2, ch = idx & 3;
                const long long grow =
                    (t < 2) ? (long long)mb * 128 + row : (long long)nb * 128 + row;
                const bool ok = (t < 2) ? (grow < M) : (grow < N);
                const __nv_bfloat16* src = srcs[t] + grow * KDIM + kt * BK + ch * 8;
                const uint32_t dst = sb + st * STAGE_SB + t * TILE_SB + row * ROWB + ch * 16;
                const int sz = ok ? 16 : 0;
                asm volatile("cp.async.cg.shared.global [%0], [%1], 16, %2;"
                             :: "r"(dst), "l"(src), "r"(sz) : "memory");
            }
        }
        asm volatile("cp.async.commit_group;" ::: "memory");
    };

    const int lr = lid & 15;
    const int lc = lid >> 4;

    load_stage(0, 0);
    load_stage(1, 1);
    load_stage(2, 2);

    for (int kt = 0; kt < KT_N; kt++) {
        if (kt < KT_N - 2)
            asm volatile("cp.async.wait_group 2;" ::: "memory");
        else if (kt == KT_N - 2)
            asm volatile("cp.async.wait_group 1;" ::: "memory");
        else
            asm volatile("cp.async.wait_group 0;" ::: "memory");
        __syncthreads();
        if (kt + 3 < KT_N) load_stage((kt + 3) & 3, kt + 3);

        const uint32_t stg = sb + (kt & 3) * STAGE_SB;
        const uint32_t aBaseHi = stg + 0 * TILE_SB;
        const uint32_t aBaseLo = stg + 1 * TILE_SB;
        const uint32_t bBaseHi = stg + 2 * TILE_SB;
        const uint32_t bBaseLo = stg + 3 * TILE_SB;

#pragma unroll
        for (int k16 = 0; k16 < 2; k16++) {
            const uint32_t koff = k16 * 32 + lc * 16;

            uint32_t ahi[2][4], alo[2][4];
#pragma unroll
            for (int mf = 0; mf < 2; mf++) {
                const uint32_t roff = (uint32_t)(wm * 32 + mf * 16 + lr) * ROWB + koff;
                ldm_x4(aBaseHi + roff, ahi[mf]);
                ldm_x4(aBaseLo + roff, alo[mf]);
            }
#pragma unroll
            for (int reg = 0; reg < 4; reg++) {
                const uint32_t roff = (uint32_t)(wn * 64 + reg * 16 + lr) * ROWB + koff;
                uint32_t bh[4], bl2[4];
                ldm_x4(bBaseHi + roff, bh);
                ldm_x4(bBaseLo + roff, bl2);
#pragma unroll
                for (int mf = 0; mf < 2; mf++) {
                    mma_bf16(acc[mf][reg * 2 + 0], ahi[mf], bh[0], bh[2]);
                    mma_bf16(acc[mf][reg * 2 + 0], ahi[mf], bl2[0], bl2[2]);
                    mma_bf16(acc[mf][reg * 2 + 0], alo[mf], bh[0], bh[2]);
                    mma_bf16(acc[mf][reg * 2 + 1], ahi[mf], bh[1], bh[3]);
                    mma_bf16(acc[mf][reg * 2 + 1], ahi[mf], bl2[1], bl2[3]);
                    mma_bf16(acc[mf][reg * 2 + 1], alo[mf], bh[1], bh[3]);
                }
            }
        }
    }

    const int lr4 = lid >> 2;
    const int lc2 = (lid & 3) * 2;
#pragma unroll
    for (int mf = 0; mf < 2; mf++) {
#pragma unroll
        for (int nf = 0; nf < 8; nf++) {
            const int m = mb * 128 + wm * 32 + mf * 16 + lr4;
            const int n = nb * 128 + wn * 64 + nf * 8 + lc2;
            if (n >= N) continue;
            float b0 = 0.f, b1 = 0.f;
            if (bias) { b0 = bias[n]; b1 = bias[n + 1]; }
            if (m < M) {
                float2 v = make_float2(acc[mf][nf][0] + b0, acc[mf][nf][1] + b1);
                *reinterpret_cast<float2*>(C + (long long)m * ldc + n) = v;
            }
            if (m + 8 < M) {
                float2 v = make_float2(acc[mf][nf][2] + b0, acc[mf][nf][3] + b1);
                *reinterpret_cast<float2*>(C + (long long)(m + 8) * ldc + n) = v;
            }
        }
    }
}

// =================== persistent recurrence kernel v4 (tensor cores) =========
// 128 CTAs = 4 bg(32 batch rows) x 32 cg(16 out cols). 256 threads = 8 warps
// (2 m-frags x 4 k-slices). Weights bf16 hi/lo smem-resident, XOR-swizzled
// 1024B rows (no padding). Separate h0 / h1 smem buffers so h1 staging
// overlaps pass A. k-slice reduction aliases the h0 buffer (dead by then).

#define RNN_CTAS 128
#define RNN_THR 256
#define WT16 16384                        // 16-row tile bytes (16*1024)
#define HT32 32768                        // 32-row tile bytes
#define OFF_W 0                           // 6 weight tiles: W0h,Wlx,Wlh x hi/lo
#define OFF_H0 (6 * WT16)                 // 98304: h0 hi, then h0 lo
#define OFF_H1 (OFF_H0 + 2 * HT32)        // 163840: h1 hi, then h1 lo
#define RNN_SMEM (OFF_H1 + 2 * HT32)      // 229376
#define OFF_R OFF_H0                      // fp32 reduction aliases h0 buffer
#define REDSTR 17

__device__ __forceinline__ void grid_bar(unsigned int target) {
    __syncthreads();
    if (threadIdx.x == 0) {
        unsigned int* p = &g_sync;
        asm volatile("red.release.gpu.global.add.u32 [%0], 1;" :: "l"(p) : "memory");
        unsigned int v;
        do {
            asm volatile("ld.acquire.gpu.global.u32 %0, [%1];" : "=r"(v) : "l"(p) : "memory");
        } while (v < target);
    }
    __syncthreads();
}

__global__ __launch_bounds__(RNN_THR, 1)
void rnn_persist(const int* __restrict__ inputs,
                 const float* __restrict__ W0,
                 const float* __restrict__ b0,
                 const float* __restrict__ Wl,
                 const float* __restrict__ bl) {
    extern __shared__ char smc[];
    const uint32_t sbase = smem_u32(smc);
    float* const smf = reinterpret_cast<float*>(smc);
    const int tid = threadIdx.x;
    const int wid = tid >> 5, lid = tid & 31;
    const int bg = blockIdx.x >> 5;
    const int cg = blockIdx.x & 31;
    const int cbase = cg * 16;

    // ---- split weight slices into smem bf16 hi/lo tiles (once, swizzled) ----
    for (int i = tid; i < 16 * 512; i += RNN_THR) {
        const int r = i >> 9, k = i & 511;
        const int gc = cbase + r;
        const uint32_t off = r * 1024 + (((k >> 3) ^ (r & 7)) << 4) + (k & 7) * 2;
        float v[3];
        v[0] = W0[gc * 1024 + k];         // W0h (x h0)
        v[1] = Wl[gc * 1024 + 512 + k];   // Wlx (x h0)
        v[2] = Wl[gc * 1024 + k];         // Wlh (x h1)
#pragma unroll
        for (int t = 0; t < 3; t++) {
            const __nv_bfloat16 hi = __float2bfloat16(v[t]);
            const __nv_bfloat16 lo = __float2bfloat16(v[t] - __bfloat162float(hi));
            char* base = smc + OFF_W + (2 * t) * WT16 + off;
            *reinterpret_cast<__nv_bfloat16*>(base) = hi;
            *reinterpret_cast<__nv_bfloat16*>(base + WT16) = lo;
        }
    }
    __syncthreads();

    const int mw = wid & 1;               // m-frag: rows mw*16..+15
    const int kw = wid >> 1;              // k-slice: chunks [kw*16, kw*16+16)
    const int lr = lid & 15, lc = lid >> 4;

    const int ecoll = tid & 15, erow = tid >> 4;
    const int ecol = cbase + ecoll;
    const float b0c = b0[ecol], blc = bl[ecol];

    const int arow = mw * 16 + lr;
    const uint32_t aRowH0 = sbase + OFF_H0 + arow * 1024;
    const uint32_t aRowH1 = sbase + OFF_H1 + arow * 1024;
    const uint32_t bRow = sbase + OFF_W + lr * 1024;
    const int axor = arow & 7;
    const int bxor = lr & 7;
    const int c0 = kw * 16 + lc;          // logical 16B-chunk base for this thread

    // staging helper: 2 tiles (hi, lo) of 32 rows x 64 chunks
    auto stage_h = [&](uint32_t offBase, const __nv_bfloat16* hi,
                       const __nv_bfloat16* lo) {
#pragma unroll
        for (int j = 0; j < 16; j++) {
            const int idx = tid + j * 256;       // 0..4095
            const int tile = idx >> 11;
            const int c = idx & 2047;
            const int row = c >> 6, ch = c & 63;
            const __nv_bfloat16* src =
                (tile ? lo : hi) + (long long)(bg * 32 + row) * HH + ch * 8;
            const uint32_t dst = sbase + offBase + tile * HT32 + row * 1024 +
                                 ((ch ^ (row & 7)) << 4);
            asm volatile("cp.async.cg.shared.global [%0], [%1], 16;"
                         :: "r"(dst), "l"(src) : "memory");
        }
        asm volatile("cp.async.commit_group;" ::: "memory");
    };

    for (int p = 0; p <= SS; p++) {
        float acc0[2][4] = {{0, 0, 0, 0}, {0, 0, 0, 0}};
        float acc1[2][4] = {{0, 0, 0, 0}, {0, 0, 0, 0}};

        // issue BOTH h0 and h1 stages; h1 completes during pass A
        stage_h(OFF_H0, g_h0bh[(p + 1) & 1], g_h0bl[(p + 1) & 1]);
        stage_h(OFF_H1, g_h1bh[p & 1], g_h1bl[p & 1]);
        asm volatile("cp.async.wait_group 1;" ::: "memory");   // h0 ready
        __syncthreads();

        // ---- pass A: h0 x W0h -> acc0 ; h0 x Wlx -> acc1 ----
#pragma unroll
        for (int i = 0; i < 8; i++) {
            const uint32_t sc = (uint32_t)((c0 + i * 2) ^ axor) << 4;
            const uint32_t wc = (uint32_t)((c0 + i * 2) ^ bxor) << 4;
            uint32_t ah[4], al[4], b0h[4], b0l[4], bxh[4], bxl[4];
            ldm_x4(aRowH0 + sc, ah);
            ldm_x4(aRowH0 + HT32 + sc, al);
            ldm_x4(bRow + 0 * WT16 + wc, b0h);
            ldm_x4(bRow + 1 * WT16 + wc, b0l);
            ldm_x4(bRow + 2 * WT16 + wc, bxh);
            ldm_x4(bRow + 3 * WT16 + wc, bxl);
            mma_bf16(acc0[0], ah, b0h[0], b0h[2]);
            mma_bf16(acc0[1], ah, b0h[1], b0h[3]);
            mma_bf16(acc0[0], ah, b0l[0], b0l[2]);
            mma_bf16(acc0[1], ah, b0l[1], b0l[3]);
            mma_bf16(acc0[0], al, b0h[0], b0h[2]);
            mma_bf16(acc0[1], al, b0h[1], b0h[3]);
            mma_bf16(acc1[0], ah, bxh[0], bxh[2]);
            mma_bf16(acc1[1], ah, bxh[1], bxh[3]);
            mma_bf16(acc1[0], ah, bxl[0], bxl[2]);
            mma_bf16(acc1[1], ah, bxl[1], bxl[3]);
            mma_bf16(acc1[0], al, bxh[0], bxh[2]);
            mma_bf16(acc1[1], al, bxh[1], bxh[3]);
        }

        asm volatile("cp.async.wait_group 0;" ::: "memory");   // h1 ready
        __syncthreads();   // h1 visible to all; pass-A h0 reads done (red alias safe)

        // ---- pass B: h1 x Wlh -> acc1 ----
#pragma unroll
        for (int i = 0; i < 8; i++) {
            const uint32_t sc = (uint32_t)((c0 + i * 2) ^ axor) << 4;
            const uint32_t wc = (uint32_t)((c0 + i * 2) ^ bxor) << 4;
            uint32_t ah[4], al[4], bhh[4], bhl[4];
            ldm_x4(aRowH1 + sc, ah);
            ldm_x4(aRowH1 + HT32 + sc, al);
            ldm_x4(bRow + 4 * WT16 + wc, bhh);
            ldm_x4(bRow + 5 * WT16 + wc, bhl);
            mma_bf16(acc1[0], ah, bhh[0], bhh[2]);
            mma_bf16(acc1[1], ah, bhh[1], bhh[3]);
            mma_bf16(acc1[0], ah, bhl[0], bhl[2]);
            mma_bf16(acc1[1], ah, bhl[1], bhl[3]);
            mma_bf16(acc1[0], al, bhh[0], bhh[2]);
            mma_bf16(acc1[1], al, bhh[1], bhh[3]);
        }

        // ---- write k-slice frags to red (aliases h0 buffer) ----
        {
            const int rg = lid >> 2, cc = (lid & 3) * 2;
            float* red = smf + OFF_R / 4;
            const int m = mw * 16 + rg;
#pragma unroll
            for (int nf = 0; nf < 2; nf++) {
                const int n = nf * 8 + cc;
                float* r0 = red + ((0 * 4 + kw) * 32 + m) * REDSTR + n;
                float* r1 = red + ((1 * 4 + kw) * 32 + m) * REDSTR + n;
                r0[0] = acc0[nf][0]; r0[1] = acc0[nf][1];
                r0[8 * REDSTR] = acc0[nf][2]; r0[8 * REDSTR + 1] = acc0[nf][3];
                r1[0] = acc1[nf][0]; r1[1] = acc1[nf][1];
                r1[8 * REDSTR] = acc1[nf][2]; r1[8 * REDSTR + 1] = acc1[nf][3];
            }
        }
        __syncthreads();

        // ---- epilogue: reduce 4 k-slices, tanh, emit hi/lo ----
        {
            float* red = smf + OFF_R / 4;
#pragma unroll
            for (int e = 0; e < 2; e++) {
                const int row = erow + e * 16;
                const int gbr = bg * 32 + row;
                float s0 = 0.f, s1 = 0.f;
#pragma unroll
                for (int q = 0; q < 4; q++) {
                    s0 += red[((0 * 4 + q) * 32 + row) * REDSTR + ecoll];
                    s1 += red[((1 * 4 + q) * 32 + row) * REDSTR + ecoll];
                }
                const long long o = (long long)gbr * HH + ecol;
                if (p < SS) {
                    const int tok = inputs[p * BB + gbr];
                    const float v = tanhf(s0 + g_P[tok * HH + ecol] + b0c);
                    const __nv_bfloat16 hv = __float2bfloat16(v);
                    const __nv_bfloat16 lv = __float2bfloat16(v - __bfloat162float(hv));
                    g_h0bh[p & 1][o] = hv;
                    g_h0bl[p & 1][o] = lv;
                    if (p == SS - 1) g_h0f[o] = v;
                }
                if (p >= 1) {
                    const int s = p - 1;
                    const float v = tanhf(s1 + blc);
                    const __nv_bfloat16 hv = __float2bfloat16(v);
                    const __nv_bfloat16 lv = __float2bfloat16(v - __bfloat162float(hv));
                    g_h1bh[(p + 1) & 1][o] = hv;
                    g_h1bl[(p + 1) & 1][o] = lv;
                    const long long ot = ((long long)s * BB + gbr) * HH + ecol;
                    g_Thi[ot] = hv;
                    g_Tlo[ot] = lv;
                    if (p == SS) g_h1f[o] = v;
                }
            }
        }

        if (p < SS) grid_bar((unsigned)(p + 1) * RNN_CTAS);
    }
}

// ---------------- prep kernels -----------------------------------------------
__global__ void prep_w0x(const float* __restrict__ W0) {
    int idx = blockIdx.x * blockDim.x + threadIdx.x;
    if (idx >= HH * EE) return;
    int c = idx / EE;
    int e = idx % EE;
    float v = W0[c * (HH + EE) + HH + e];
    __nv_bfloat16 hi = __float2bfloat16(v);
    g_Xhi[c * EE + e] = hi;
    g_Xlo[c * EE + e] = __float2bfloat16(v - __bfloat162float(hi));
}

__global__ void split_arr(const float* __restrict__ src, __nv_bfloat16* __restrict__ hi,
                          __nv_bfloat16* __restrict__ lo, int n, float scale) {
    int i = blockIdx.x * blockDim.x + threadIdx.x;
    if (i >= n) return;
    float v = src[i] * scale;
    __nv_bfloat16 h = __float2bfloat16(v);
    hi[i] = h;
    lo[i] = __float2bfloat16(v - __bfloat162float(h));
}

__global__ void init_state(const float* __restrict__ hidden) {
    int i = blockIdx.x * blockDim.x + threadIdx.x;
    if (i == 0) g_sync = 0;
    if (i < BB * HH) {
        float v0 = hidden[i];
        __nv_bfloat16 h0 = __float2bfloat16(v0);
        g_h0bh[1][i] = h0;
        g_h0bl[1][i] = __float2bfloat16(v0 - __bfloat162float(h0));
        float v1 = hidden[BB * HH + i];
        __nv_bfloat16 h1 = __float2bfloat16(v1);
        g_h1bh[1][i] = h1;
        g_h1bl[1][i] = __float2bfloat16(v1 - __bfloat162float(h1));
    }
}

__global__ void write_hfinal(float* __restrict__ out) {
    int i = blockIdx.x * blockDim.x + threadIdx.x;
    if (i < BB * HH) {
        out[i] = g_h0f[i];
        out[BB * HH + i] = g_h1f[i];
    }
}

// ---------------- launch ------------------------------------------------------
extern "C" void kernel_launch(void* const* d_in, const int* in_sizes, int n_in,
                              void* d_out, int out_size) {
    const int*   inputs = (const int*)  d_in[0];
    const float* hidden = (const float*)d_in[1];
    const float* emb    = (const float*)d_in[2];
    const float* W0     = (const float*)d_in[3];
    const float* b0     = (const float*)d_in[4];
    const float* Wl     = (const float*)d_in[5];
    const float* bl     = (const float*)d_in[6];
    const float* Wout   = (const float*)d_in[7];
    const float* bout   = (const float*)d_in[8];

    float* logits = (float*)d_out;
    float* hfin   = (float*)d_out + (long long)SS * BB * VV;

    cudaFuncSetAttribute(gemm_hmma, cudaFuncAttributeMaxDynamicSharedMemorySize,
                         GEMM_SMEM);
    cudaFuncSetAttribute(rnn_persist, cudaFuncAttributeMaxDynamicSharedMemorySize,
                         RNN_SMEM);

    float* pP = nullptr;
    cudaGetSymbolAddress((void**)&pP, g_P);
    __nv_bfloat16 *pThi, *pTlo, *pWhi, *pWlo, *pEhi, *pElo, *pXhi, *pXlo;
    cudaGetSymbolAddress((void**)&pThi, g_Thi);
    cudaGetSymbolAddress((void**)&pTlo, g_Tlo);
    cudaGetSymbolAddress((void**)&pWhi, g_Whi);
    cudaGetSymbolAddress((void**)&pWlo, g_Wlo);
    cudaGetSymbolAddress((void**)&pEhi, g_Ehi);
    cudaGetSymbolAddress((void**)&pElo, g_Elo);
    cudaGetSymbolAddress((void**)&pXhi, g_Xhi);
    cudaGetSymbolAddress((void**)&pXlo, g_Xlo);

    const float scale = 22.62741699796952f;  // sqrt(512)

    // 1. prep
    init_state<<<(BB * HH + 255) / 256, 256>>>(hidden);
    prep_w0x<<<(HH * EE + 255) / 256, 256>>>(W0);
    split_arr<<<(VV * EE + 255) / 256, 256>>>(emb, pEhi, pElo, VV * EE, scale);
    split_arr<<<(VV * HH + 255) / 256, 256>>>(Wout, pWhi, pWlo, VV * HH, 1.0f);

    // 2. P = scale*emb @ W0x^T  (M=10000, N=512, K=512)
    {
        dim3 grid((HH + 127) / 128, (VV + 127) / 128);
        gemm_hmma<<<grid, 256, GEMM_SMEM>>>(pEhi, pElo, pXhi, pXlo,
                                            VV, HH, pP, HH, nullptr);
    }

    // 3. full recurrence in ONE persistent kernel (tensor cores)
    rnn_persist<<<RNN_CTAS, RNN_THR, RNN_SMEM>>>(inputs, W0, b0, Wl, bl);

    // 4. logits = tops @ Wout^T + bout  (M=16384, N=10000, K=512)
    {
        dim3 grid((VV + 127) / 128, (SS * BB + 127) / 128);
        gemm_hmma<<<grid, 256, GEMM_SMEM>>>(pThi, pTlo, pWhi, pWlo,
                                            SS * BB, VV, logits, VV, bout);
    }

    // 5. final hidden state
    write_hfinal<<<(BB * HH + 255) / 256, 256>>>(hfin);
}

// round 10
// speedup vs baseline: 1.8650x; 1.1492x over previous
#include <cuda_runtime.h>
#include <cuda_bf16.h>
#include <math.h>
#include <stdint.h>

#define SS 128
#define BB 128
#define VV 10000
#define HH 512
#define EE 512
#define KDIM 512

// ---------------- scratch (device globals: no allocations allowed) ----------
__device__ float g_P[VV * HH];          // scale * emb @ W0_x^T
__device__ unsigned int g_sync;         // grid barrier counter
// hidden state as bf16 hi/lo ping-pong (MMA operands)
__device__ __nv_bfloat16 g_h0bh[2][BB * HH], g_h0bl[2][BB * HH];
__device__ __nv_bfloat16 g_h1bh[2][BB * HH], g_h1bl[2][BB * HH];
__device__ float g_h0f[BB * HH], g_h1f[BB * HH];   // fp32 finals
// bf16 hi/lo split operands for tensor GEMMs
__device__ __nv_bfloat16 g_Thi[SS * BB * HH];
__device__ __nv_bfloat16 g_Tlo[SS * BB * HH];
__device__ __nv_bfloat16 g_Whi[VV * HH];
__device__ __nv_bfloat16 g_Wlo[VV * HH];
__device__ __nv_bfloat16 g_Ehi[VV * EE];
__device__ __nv_bfloat16 g_Elo[VV * EE];
__device__ __nv_bfloat16 g_Xhi[HH * EE];
__device__ __nv_bfloat16 g_Xlo[HH * EE];

// ============================ helpers ========================================
__device__ __forceinline__ uint32_t smem_u32(const void* p) {
    uint32_t a;
    asm("{ .reg .u64 t; cvta.to.shared.u64 t, %1; cvt.u32.u64 %0, t; }"
        : "=r"(a) : "l"(p));
    return a;
}

__device__ __forceinline__ void ldm_x4(uint32_t addr, uint32_t r[4]) {
    asm volatile("ldmatrix.sync.aligned.m8n8.x4.shared.b16 {%0,%1,%2,%3}, [%4];"
                 : "=r"(r[0]), "=r"(r[1]), "=r"(r[2]), "=r"(r[3]) : "r"(addr));
}

__device__ __forceinline__ void mma_bf16(float c[4], const uint32_t a[4],
                                         uint32_t b0, uint32_t b1) {
    asm volatile(
        "mma.sync.aligned.m16n8k16.row.col.f32.bf16.bf16.f32 "
        "{%0,%1,%2,%3}, {%4,%5,%6,%7}, {%8,%9}, {%0,%1,%2,%3};"
        : "+f"(c[0]), "+f"(c[1]), "+f"(c[2]), "+f"(c[3])
        : "r"(a[0]), "r"(a[1]), "r"(a[2]), "r"(a[3]), "r"(b0), "r"(b1));
}

// =================== bf16-split HMMA GEMM, 2-stage, 2 CTAs/SM ================
#define BK 32
#define ROWB 80
#define TILE_SB (128 * ROWB)
#define STAGE_SB (4 * TILE_SB)
#define GEMM_SMEM (2 * STAGE_SB)       // 81920 -> two CTAs co-resident per SM
#define KT_N (KDIM / BK)               // 16

__global__ __launch_bounds__(256, 2)
void gemm_hmma(const __nv_bfloat16* __restrict__ Ahi,
               const __nv_bfloat16* __restrict__ Alo,
               const __nv_bfloat16* __restrict__ Bhi,
               const __nv_bfloat16* __restrict__ Blo,
               int M, int N, float* __restrict__ C, int ldc,
               const float* __restrict__ bias) {
    extern __shared__ char smem[];
    const uint32_t sb = smem_u32(smem);
    const int tid = threadIdx.x;
    const int wid = tid >> 5, lid = tid & 31;
    const int wm = wid & 3, wn = wid >> 2;
    const int nb = blockIdx.x, mb = blockIdx.y;

    const __nv_bfloat16* __restrict__ srcs[4] = {Ahi, Alo, Bhi, Blo};

    float acc[2][8][4];
#pragma unroll
    for (int i = 0; i < 2; i++)
#pragma unroll
        for (int j = 0; j < 8; j++)
#pragma unroll
            for (int q = 0; q < 4; q++) acc[i][j][q] = 0.0f;

    auto load_stage = [&](int st, int kt) {
#pragma unroll
        for (int t = 0; t < 4; t++) {
#pragma unroll
            for (int i = 0; i < 2; i++) {
                const int idx = tid + i * 256;
                const int row = idx >> 2, ch = idx & 3;
                const long long grow =
                    (t < 2) ? (long long)mb * 128 + row : (long long)nb * 128 + row;
                const bool ok = (t < 2) ? (grow < M) : (grow < N);
                const __nv_bfloat16* src = srcs[t] + grow * KDIM + kt * BK + ch * 8;
                const uint32_t dst = sb + st * STAGE_SB + t * TILE_SB + row * ROWB + ch * 16;
                const int sz = ok ? 16 : 0;
                asm volatile("cp.async.cg.shared.global [%0], [%1], 16, %2;"
                             :: "r"(dst), "l"(src), "r"(sz) : "memory");
            }
        }
        asm volatile("cp.async.commit_group;" ::: "memory");
    };

    const int lr = lid & 15;
    const int lc = lid >> 4;

    load_stage(0, 0);

    for (int kt = 0; kt < KT_N; kt++) {
        const int st = kt & 1;
        if (kt + 1 < KT_N) {
            load_stage(st ^ 1, kt + 1);
            asm volatile("cp.async.wait_group 1;" ::: "memory");
        } else {
            asm volatile("cp.async.wait_group 0;" ::: "memory");
        }
        __syncthreads();

        const uint32_t stg = sb + st * STAGE_SB;
        const uint32_t aBaseHi = stg + 0 * TILE_SB;
        const uint32_t aBaseLo = stg + 1 * TILE_SB;
        const uint32_t bBaseHi = stg + 2 * TILE_SB;
        const uint32_t bBaseLo = stg + 3 * TILE_SB;

#pragma unroll
        for (int k16 = 0; k16 < 2; k16++) {
            const uint32_t koff = k16 * 32 + lc * 16;

            uint32_t ahi[2][4], alo[2][4];
#pragma unroll
            for (int mf = 0; mf < 2; mf++) {
                const uint32_t roff = (uint32_t)(wm * 32 + mf * 16 + lr) * ROWB + koff;
                ldm_x4(aBaseHi + roff, ahi[mf]);
                ldm_x4(aBaseLo + roff, alo[mf]);
            }
#pragma unroll
            for (int reg = 0; reg < 4; reg++) {
                const uint32_t roff = (uint32_t)(wn * 64 + reg * 16 + lr) * ROWB + koff;
                uint32_t bh[4], bl2[4];
                ldm_x4(bBaseHi + roff, bh);
                ldm_x4(bBaseLo + roff, bl2);
#pragma unroll
                for (int mf = 0; mf < 2; mf++) {
                    mma_bf16(acc[mf][reg * 2 + 0], ahi[mf], bh[0], bh[2]);
                    mma_bf16(acc[mf][reg * 2 + 0], ahi[mf], bl2[0], bl2[2]);
                    mma_bf16(acc[mf][reg * 2 + 0], alo[mf], bh[0], bh[2]);
                    mma_bf16(acc[mf][reg * 2 + 1], ahi[mf], bh[1], bh[3]);
                    mma_bf16(acc[mf][reg * 2 + 1], ahi[mf], bl2[1], bl2[3]);
                    mma_bf16(acc[mf][reg * 2 + 1], alo[mf], bh[1], bh[3]);
                }
            }
        }
        __syncthreads();
    }

    const int lr4 = lid >> 2;
    const int lc2 = (lid & 3) * 2;
#pragma unroll
    for (int mf = 0; mf < 2; mf++) {
#pragma unroll
        for (int nf = 0; nf < 8; nf++) {
            const int m = mb * 128 + wm * 32 + mf * 16 + lr4;
            const int n = nb * 128 + wn * 64 + nf * 8 + lc2;
            if (n >= N) continue;
            float b0 = 0.f, b1 = 0.f;
            if (bias) { b0 = bias[n]; b1 = bias[n + 1]; }
            if (m < M) {
                float2 v = make_float2(acc[mf][nf][0] + b0, acc[mf][nf][1] + b1);
                *reinterpret_cast<float2*>(C + (long long)m * ldc + n) = v;
            }
            if (m + 8 < M) {
                float2 v = make_float2(acc[mf][nf][2] + b0, acc[mf][nf][3] + b1);
                *reinterpret_cast<float2*>(C + (long long)(m + 8) * ldc + n) = v;
            }
        }
    }
}

// =================== persistent recurrence kernel v4 (tensor cores) =========
#define RNN_CTAS 128
#define RNN_THR 256
#define WT16 16384
#define HT32 32768
#define OFF_W 0
#define OFF_H0 (6 * WT16)
#define OFF_H1 (OFF_H0 + 2 * HT32)
#define RNN_SMEM (OFF_H1 + 2 * HT32)      // 229376
#define OFF_R OFF_H0
#define REDSTR 17

__global__ __launch_bounds__(RNN_THR, 1)
void rnn_persist(const int* __restrict__ inputs,
                 const float* __restrict__ W0,
                 const float* __restrict__ b0,
                 const float* __restrict__ Wl,
                 const float* __restrict__ bl) {
    extern __shared__ char smc[];
    const uint32_t sbase = smem_u32(smc);
    float* const smf = reinterpret_cast<float*>(smc);
    const int tid = threadIdx.x;
    const int wid = tid >> 5, lid = tid & 31;
    const int bg = blockIdx.x >> 5;
    const int cg = blockIdx.x & 31;
    const int cbase = cg * 16;

    // ---- split weight slices into smem bf16 hi/lo tiles (once, swizzled) ----
    for (int i = tid; i < 16 * 512; i += RNN_THR) {
        const int r = i >> 9, k = i & 511;
        const int gc = cbase + r;
        const uint32_t off = r * 1024 + (((k >> 3) ^ (r & 7)) << 4) + (k & 7) * 2;
        float v[3];
        v[0] = W0[gc * 1024 + k];
        v[1] = Wl[gc * 1024 + 512 + k];
        v[2] = Wl[gc * 1024 + k];
#pragma unroll
        for (int t = 0; t < 3; t++) {
            const __nv_bfloat16 hi = __float2bfloat16(v[t]);
            const __nv_bfloat16 lo = __float2bfloat16(v[t] - __bfloat162float(hi));
            char* base = smc + OFF_W + (2 * t) * WT16 + off;
            *reinterpret_cast<__nv_bfloat16*>(base) = hi;
            *reinterpret_cast<__nv_bfloat16*>(base + WT16) = lo;
        }
    }
    __syncthreads();

    const int mw = wid & 1;
    const int kw = wid >> 1;
    const int lr = lid & 15, lc = lid >> 4;

    const int ecoll = tid & 15, erow = tid >> 4;
    const int ecol = cbase + ecoll;
    const float b0c = b0[ecol], blc = bl[ecol];

    const int arow = mw * 16 + lr;
    const uint32_t aRowH0 = sbase + OFF_H0 + arow * 1024;
    const uint32_t aRowH1 = sbase + OFF_H1 + arow * 1024;
    const uint32_t bRow = sbase + OFF_W + lr * 1024;
    const int axor = arow & 7;
    const int bxor = lr & 7;
    const int c0 = kw * 16 + lc;

    auto stage_h = [&](uint32_t offBase, const __nv_bfloat16* hi,
                       const __nv_bfloat16* lo) {
#pragma unroll
        for (int j = 0; j < 16; j++) {
            const int idx = tid + j * 256;
            const int tile = idx >> 11;
            const int c = idx & 2047;
            const int row = c >> 6, ch = c & 63;
            const __nv_bfloat16* src =
                (tile ? lo : hi) + (long long)(bg * 32 + row) * HH + ch * 8;
            const uint32_t dst = sbase + offBase + tile * HT32 + row * 1024 +
                                 ((ch ^ (row & 7)) << 4);
            asm volatile("cp.async.cg.shared.global [%0], [%1], 16;"
                         :: "r"(dst), "l"(src) : "memory");
        }
        asm volatile("cp.async.commit_group;" ::: "memory");
    };

    for (int p = 0; p <= SS; p++) {
        float acc0[2][4] = {{0, 0, 0, 0}, {0, 0, 0, 0}};
        float acc1[2][4] = {{0, 0, 0, 0}, {0, 0, 0, 0}};

        stage_h(OFF_H0, g_h0bh[(p + 1) & 1], g_h0bl[(p + 1) & 1]);
        stage_h(OFF_H1, g_h1bh[p & 1], g_h1bl[p & 1]);
        asm volatile("cp.async.wait_group 1;" ::: "memory");   // h0 ready
        __syncthreads();

        // ---- pass A: h0 x W0h -> acc0 ; h0 x Wlx -> acc1 ----
#pragma unroll
        for (int i = 0; i < 8; i++) {
            const uint32_t sc = (uint32_t)((c0 + i * 2) ^ axor) << 4;
            const uint32_t wc = (uint32_t)((c0 + i * 2) ^ bxor) << 4;
            uint32_t ah[4], al[4], b0h[4], b0l[4], bxh[4], bxl[4];
            ldm_x4(aRowH0 + sc, ah);
            ldm_x4(aRowH0 + HT32 + sc, al);
            ldm_x4(bRow + 0 * WT16 + wc, b0h);
            ldm_x4(bRow + 1 * WT16 + wc, b0l);
            ldm_x4(bRow + 2 * WT16 + wc, bxh);
            ldm_x4(bRow + 3 * WT16 + wc, bxl);
            mma_bf16(acc0[0], ah, b0h[0], b0h[2]);
            mma_bf16(acc0[1], ah, b0h[1], b0h[3]);
            mma_bf16(acc0[0], ah, b0l[0], b0l[2]);
            mma_bf16(acc0[1], ah, b0l[1], b0l[3]);
            mma_bf16(acc0[0], al, b0h[0], b0h[2]);
            mma_bf16(acc0[1], al, b0h[1], b0h[3]);
            mma_bf16(acc1[0], ah, bxh[0], bxh[2]);
            mma_bf16(acc1[1], ah, bxh[1], bxh[3]);
            mma_bf16(acc1[0], ah, bxl[0], bxl[2]);
            mma_bf16(acc1[1], ah, bxl[1], bxl[3]);
            mma_bf16(acc1[0], al, bxh[0], bxh[2]);
            mma_bf16(acc1[1], al, bxh[1], bxh[3]);
        }

        asm volatile("cp.async.wait_group 0;" ::: "memory");   // h1 ready
        __syncthreads();

        // ---- pass B: h1 x Wlh -> acc1 ----
#pragma unroll
        for (int i = 0; i < 8; i++) {
            const uint32_t sc = (uint32_t)((c0 + i * 2) ^ axor) << 4;
            const uint32_t wc = (uint32_t)((c0 + i * 2) ^ bxor) << 4;
            uint32_t ah[4], al[4], bhh[4], bhl[4];
            ldm_x4(aRowH1 + sc, ah);
            ldm_x4(aRowH1 + HT32 + sc, al);
            ldm_x4(bRow + 4 * WT16 + wc, bhh);
            ldm_x4(bRow + 5 * WT16 + wc, bhl);
            mma_bf16(acc1[0], ah, bhh[0], bhh[2]);
            mma_bf16(acc1[1], ah, bhh[1], bhh[3]);
            mma_bf16(acc1[0], ah, bhl[0], bhl[2]);
            mma_bf16(acc1[1], ah, bhl[1], bhl[3]);
            mma_bf16(acc1[0], al, bhh[0], bhh[2]);
            mma_bf16(acc1[1], al, bhh[1], bhh[3]);
        }

        // ---- write k-slice frags to red (aliases h0 buffer) ----
        {
            const int rg = lid >> 2, cc = (lid & 3) * 2;
            float* red = smf + OFF_R / 4;
            const int m = mw * 16 + rg;
#pragma unroll
            for (int nf = 0; nf < 2; nf++) {
                const int n = nf * 8 + cc;
                float* r0 = red + ((0 * 4 + kw) * 32 + m) * REDSTR + n;
                float* r1 = red + ((1 * 4 + kw) * 32 + m) * REDSTR + n;
                r0[0] = acc0[nf][0]; r0[1] = acc0[nf][1];
                r0[8 * REDSTR] = acc0[nf][2]; r0[8 * REDSTR + 1] = acc0[nf][3];
                r1[0] = acc1[nf][0]; r1[1] = acc1[nf][1];
                r1[8 * REDSTR] = acc1[nf][2]; r1[8 * REDSTR + 1] = acc1[nf][3];
            }
        }
        __syncthreads();

        // ---- epilogue: reduce, tanh, store h state; arrive; then tops ----
        float v1s[2];
        __nv_bfloat16 hv1s[2], lv1s[2];
        {
            float* red = smf + OFF_R / 4;
#pragma unroll
            for (int e = 0; e < 2; e++) {
                const int row = erow + e * 16;
                const int gbr = bg * 32 + row;
                float s0 = 0.f, s1 = 0.f;
#pragma unroll
                for (int q = 0; q < 4; q++) {
                    s0 += red[((0 * 4 + q) * 32 + row) * REDSTR + ecoll];
                    s1 += red[((1 * 4 + q) * 32 + row) * REDSTR + ecoll];
                }
                const long long o = (long long)gbr * HH + ecol;
                if (p < SS) {
                    const int tok = inputs[p * BB + gbr];
                    const float v = tanhf(s0 + g_P[tok * HH + ecol] + b0c);
                    const __nv_bfloat16 hv = __float2bfloat16(v);
                    const __nv_bfloat16 lv = __float2bfloat16(v - __bfloat162float(hv));
                    g_h0bh[p & 1][o] = hv;
                    g_h0bl[p & 1][o] = lv;
                    if (p == SS - 1) g_h0f[o] = v;
                }
                if (p >= 1) {
                    const float v = tanhf(s1 + blc);
                    const __nv_bfloat16 hv = __float2bfloat16(v);
                    const __nv_bfloat16 lv = __float2bfloat16(v - __bfloat162float(hv));
                    g_h1bh[(p + 1) & 1][o] = hv;
                    g_h1bl[(p + 1) & 1][o] = lv;
                    v1s[e] = v; hv1s[e] = hv; lv1s[e] = lv;
                    if (p == SS) g_h1f[o] = v;
                }
            }
        }

        // arrive on the grid barrier BEFORE the tops stores (tops are not
        // read by any rnn CTA; the release orders the h stores above).
        if (p < SS) {
            __syncthreads();
            if (tid == 0) {
                unsigned int* gp = &g_sync;
                asm volatile("red.release.gpu.global.add.u32 [%0], 1;"
                             :: "l"(gp) : "memory");
            }
        }

        if (p >= 1) {
            const int s = p - 1;
#pragma unroll
            for (int e = 0; e < 2; e++) {
                const int gbr = bg * 32 + erow + e * 16;
                const long long ot = ((long long)s * BB + gbr) * HH + ecol;
                g_Thi[ot] = hv1s[e];
                g_Tlo[ot] = lv1s[e];
            }
        }

        if (p < SS) {
            if (tid == 0) {
                const unsigned int target = (unsigned)(p + 1) * RNN_CTAS;
                unsigned int* gp = &g_sync;
                unsigned int v;
                do {
                    asm volatile("ld.acquire.gpu.global.u32 %0, [%1];"
                                 : "=r"(v) : "l"(gp) : "memory");
                } while (v < target);
            }
            __syncthreads();
        }
    }
}

// ---------------- prep kernels -----------------------------------------------
__global__ void prep_w0x(const float* __restrict__ W0) {
    int idx = blockIdx.x * blockDim.x + threadIdx.x;
    if (idx >= HH * EE) return;
    int c = idx / EE;
    int e = idx % EE;
    float v = W0[c * (HH + EE) + HH + e];
    __nv_bfloat16 hi = __float2bfloat16(v);
    g_Xhi[c * EE + e] = hi;
    g_Xlo[c * EE + e] = __float2bfloat16(v - __bfloat162float(hi));
}

__global__ void split_arr(const float* __restrict__ src, __nv_bfloat16* __restrict__ hi,
                          __nv_bfloat16* __restrict__ lo, int n, float scale) {
    int i = blockIdx.x * blockDim.x + threadIdx.x;
    if (i >= n) return;
    float v = src[i] * scale;
    __nv_bfloat16 h = __float2bfloat16(v);
    hi[i] = h;
    lo[i] = __float2bfloat16(v - __bfloat162float(h));
}

__global__ void init_state(const float* __restrict__ hidden) {
    int i = blockIdx.x * blockDim.x + threadIdx.x;
    if (i == 0) g_sync = 0;
    if (i < BB * HH) {
        float v0 = hidden[i];
        __nv_bfloat16 h0 = __float2bfloat16(v0);
        g_h0bh[1][i] = h0;
        g_h0bl[1][i] = __float2bfloat16(v0 - __bfloat162float(h0));
        float v1 = hidden[BB * HH + i];
        __nv_bfloat16 h1 = __float2bfloat16(v1);
        g_h1bh[1][i] = h1;
        g_h1bl[1][i] = __float2bfloat16(v1 - __bfloat162float(h1));
    }
}

__global__ void write_hfinal(float* __restrict__ out) {
    int i = blockIdx.x * blockDim.x + threadIdx.x;
    if (i < BB * HH) {
        out[i] = g_h0f[i];
        out[BB * HH + i] = g_h1f[i];
    }
}

// ---------------- launch ------------------------------------------------------
extern "C" void kernel_launch(void* const* d_in, const int* in_sizes, int n_in,
                              void* d_out, int out_size) {
    const int*   inputs = (const int*)  d_in[0];
    const float* hidden = (const float*)d_in[1];
    const float* emb    = (const float*)d_in[2];
    const float* W0     = (const float*)d_in[3];
    const float* b0     = (const float*)d_in[4];
    const float* Wl     = (const float*)d_in[5];
    const float* bl     = (const float*)d_in[6];
    const float* Wout   = (const float*)d_in[7];
    const float* bout   = (const float*)d_in[8];

    float* logits = (float*)d_out;
    float* hfin   = (float*)d_out + (long long)SS * BB * VV;

    cudaFuncSetAttribute(gemm_hmma, cudaFuncAttributeMaxDynamicSharedMemorySize,
                         GEMM_SMEM);
    cudaFuncSetAttribute(rnn_persist, cudaFuncAttributeMaxDynamicSharedMemorySize,
                         RNN_SMEM);

    float* pP = nullptr;
    cudaGetSymbolAddress((void**)&pP, g_P);
    __nv_bfloat16 *pThi, *pTlo, *pWhi, *pWlo, *pEhi, *pElo, *pXhi, *pXlo;
    cudaGetSymbolAddress((void**)&pThi, g_Thi);
    cudaGetSymbolAddress((void**)&pTlo, g_Tlo);
    cudaGetSymbolAddress((void**)&pWhi, g_Whi);
    cudaGetSymbolAddress((void**)&pWlo, g_Wlo);
    cudaGetSymbolAddress((void**)&pEhi, g_Ehi);
    cudaGetSymbolAddress((void**)&pElo, g_Elo);
    cudaGetSymbolAddress((void**)&pXhi, g_Xhi);
    cudaGetSymbolAddress((void**)&pXlo, g_Xlo);

    const float scale = 22.62741699796952f;  // sqrt(512)

    // 1. prep
    init_state<<<(BB * HH + 255) / 256, 256>>>(hidden);
    prep_w0x<<<(HH * EE + 255) / 256, 256>>>(W0);
    split_arr<<<(VV * EE + 255) / 256, 256>>>(emb, pEhi, pElo, VV * EE, scale);
    split_arr<<<(VV * HH + 255) / 256, 256>>>(Wout, pWhi, pWlo, VV * HH, 1.0f);

    // 2. P = scale*emb @ W0x^T  (M=10000, N=512, K=512)
    {
        dim3 grid((HH + 127) / 128, (VV + 127) / 128);
        gemm_hmma<<<grid, 256, GEMM_SMEM>>>(pEhi, pElo, pXhi, pXlo,
                                            VV, HH, pP, HH, nullptr);
    }

    // 3. full recurrence in ONE persistent kernel (tensor cores)
    rnn_persist<<<RNN_CTAS, RNN_THR, RNN_SMEM>>>(inputs, W0, b0, Wl, bl);

    // 4. logits = tops @ Wout^T + bout  (M=16384, N=10000, K=512)
    {
        dim3 grid((VV + 127) / 128, (SS * BB + 127) / 128);
        gemm_hmma<<<grid, 256, GEMM_SMEM>>>(pThi, pTlo, pWhi, pWlo,
                                            SS * BB, VV, logits, VV, bout);
    }

    // 5. final hidden state
    write_hfinal<<<(BB * HH + 255) / 256, 256>>>(hfin);
}

// round 11
// speedup vs baseline: 1.9565x; 1.0491x over previous
#include <cuda_runtime.h>
#include <cuda_bf16.h>
#include <math.h>
#include <stdint.h>

#define SS 128
#define BB 128
#define VV 10000
#define HH 512
#define EE 512
#define KDIM 512

// ---------------- scratch (device globals: no allocations allowed) ----------
__device__ float g_P[VV * HH];          // scale * emb @ W0_x^T
__device__ unsigned int g_sync4[128];   // 4 batch-group barriers, 128B apart
// hidden state as bf16 hi/lo ping-pong (MMA operands)
__device__ __nv_bfloat16 g_h0bh[2][BB * HH], g_h0bl[2][BB * HH];
__device__ __nv_bfloat16 g_h1bh[2][BB * HH], g_h1bl[2][BB * HH];
// bf16 hi/lo split operands for tensor GEMMs
__device__ __nv_bfloat16 g_Thi[SS * BB * HH];
__device__ __nv_bfloat16 g_Tlo[SS * BB * HH];
__device__ __nv_bfloat16 g_Whi[VV * HH];
__device__ __nv_bfloat16 g_Wlo[VV * HH];
__device__ __nv_bfloat16 g_Ehi[VV * EE];
__device__ __nv_bfloat16 g_Elo[VV * EE];
__device__ __nv_bfloat16 g_Xhi[HH * EE];
__device__ __nv_bfloat16 g_Xlo[HH * EE];

// ============================ helpers ========================================
__device__ __forceinline__ uint32_t smem_u32(const void* p) {
    uint32_t a;
    asm("{ .reg .u64 t; cvta.to.shared.u64 t, %1; cvt.u32.u64 %0, t; }"
        : "=r"(a) : "l"(p));
    return a;
}

__device__ __forceinline__ void ldm_x4(uint32_t addr, uint32_t r[4]) {
    asm volatile("ldmatrix.sync.aligned.m8n8.x4.shared.b16 {%0,%1,%2,%3}, [%4];"
                 : "=r"(r[0]), "=r"(r[1]), "=r"(r[2]), "=r"(r[3]) : "r"(addr));
}

__device__ __forceinline__ void mma_bf16(float c[4], const uint32_t a[4],
                                         uint32_t b0, uint32_t b1) {
    asm volatile(
        "mma.sync.aligned.m16n8k16.row.col.f32.bf16.bf16.f32 "
        "{%0,%1,%2,%3}, {%4,%5,%6,%7}, {%8,%9}, {%0,%1,%2,%3};"
        : "+f"(c[0]), "+f"(c[1]), "+f"(c[2]), "+f"(c[3])
        : "r"(a[0]), "r"(a[1]), "r"(a[2]), "r"(a[3]), "r"(b0), "r"(b1));
}

// =================== bf16-split HMMA GEMM, 2-stage, 2 CTAs/SM ================
#define BK 32
#define ROWB 80
#define TILE_SB (128 * ROWB)
#define STAGE_SB (4 * TILE_SB)
#define GEMM_SMEM (2 * STAGE_SB)       // 81920 -> two CTAs co-resident per SM
#define KT_N (KDIM / BK)               // 16

__global__ __launch_bounds__(256, 2)
void gemm_hmma(const __nv_bfloat16* __restrict__ Ahi,
               const __nv_bfloat16* __restrict__ Alo,
               const __nv_bfloat16* __restrict__ Bhi,
               const __nv_bfloat16* __restrict__ Blo,
               int M, int N, float* __restrict__ C, int ldc,
               const float* __restrict__ bias) {
    extern __shared__ char smem[];
    const uint32_t sb = smem_u32(smem);
    const int tid = threadIdx.x;
    const int wid = tid >> 5, lid = tid & 31;
    const int wm = wid & 3, wn = wid >> 2;
    const int nb = blockIdx.x, mb = blockIdx.y;

    const __nv_bfloat16* __restrict__ srcs[4] = {Ahi, Alo, Bhi, Blo};

    float acc[2][8][4];
#pragma unroll
    for (int i = 0; i < 2; i++)
#pragma unroll
        for (int j = 0; j < 8; j++)
#pragma unroll
            for (int q = 0; q < 4; q++) acc[i][j][q] = 0.0f;

    auto load_stage = [&](int st, int kt) {
#pragma unroll
        for (int t = 0; t < 4; t++) {
#pragma unroll
            for (int i = 0; i < 2; i++) {
                const int idx = tid + i * 256;
                const int row = idx >> 2, ch = idx & 3;
                const long long grow =
                    (t < 2) ? (long long)mb * 128 + row : (long long)nb * 128 + row;
                const bool ok = (t < 2) ? (grow < M) : (grow < N);
                const __nv_bfloat16* src = srcs[t] + grow * KDIM + kt * BK + ch * 8;
                const uint32_t dst = sb + st * STAGE_SB + t * TILE_SB + row * ROWB + ch * 16;
                const int sz = ok ? 16 : 0;
                asm volatile("cp.async.cg.shared.global [%0], [%1], 16, %2;"
                             :: "r"(dst), "l"(src), "r"(sz) : "memory");
            }
        }
        asm volatile("cp.async.commit_group;" ::: "memory");
    };

    const int lr = lid & 15;
    const int lc = lid >> 4;

    load_stage(0, 0);

    for (int kt = 0; kt < KT_N; kt++) {
        const int st = kt & 1;
        if (kt + 1 < KT_N) {
            load_stage(st ^ 1, kt + 1);
            asm volatile("cp.async.wait_group 1;" ::: "memory");
        } else {
            asm volatile("cp.async.wait_group 0;" ::: "memory");
        }
        __syncthreads();

        const uint32_t stg = sb + st * STAGE_SB;
        const uint32_t aBaseHi = stg + 0 * TILE_SB;
        const uint32_t aBaseLo = stg + 1 * TILE_SB;
        const uint32_t bBaseHi = stg + 2 * TILE_SB;
        const uint32_t bBaseLo = stg + 3 * TILE_SB;

#pragma unroll
        for (int k16 = 0; k16 < 2; k16++) {
            const uint32_t koff = k16 * 32 + lc * 16;

            uint32_t ahi[2][4], alo[2][4];
#pragma unroll
            for (int mf = 0; mf < 2; mf++) {
                const uint32_t roff = (uint32_t)(wm * 32 + mf * 16 + lr) * ROWB + koff;
                ldm_x4(aBaseHi + roff, ahi[mf]);
                ldm_x4(aBaseLo + roff, alo[mf]);
            }
#pragma unroll
            for (int reg = 0; reg < 4; reg++) {
                const uint32_t roff = (uint32_t)(wn * 64 + reg * 16 + lr) * ROWB + koff;
                uint32_t bh[4], bl2[4];
                ldm_x4(bBaseHi + roff, bh);
                ldm_x4(bBaseLo + roff, bl2);
#pragma unroll
                for (int mf = 0; mf < 2; mf++) {
                    mma_bf16(acc[mf][reg * 2 + 0], ahi[mf], bh[0], bh[2]);
                    mma_bf16(acc[mf][reg * 2 + 0], ahi[mf], bl2[0], bl2[2]);
                    mma_bf16(acc[mf][reg * 2 + 0], alo[mf], bh[0], bh[2]);
                    mma_bf16(acc[mf][reg * 2 + 1], ahi[mf], bh[1], bh[3]);
                    mma_bf16(acc[mf][reg * 2 + 1], ahi[mf], bl2[1], bl2[3]);
                    mma_bf16(acc[mf][reg * 2 + 1], alo[mf], bh[1], bh[3]);
                }
            }
        }
        __syncthreads();
    }

    const int lr4 = lid >> 2;
    const int lc2 = (lid & 3) * 2;
#pragma unroll
    for (int mf = 0; mf < 2; mf++) {
#pragma unroll
        for (int nf = 0; nf < 8; nf++) {
            const int m = mb * 128 + wm * 32 + mf * 16 + lr4;
            const int n = nb * 128 + wn * 64 + nf * 8 + lc2;
            if (n >= N) continue;
            float b0 = 0.f, b1 = 0.f;
            if (bias) { b0 = bias[n]; b1 = bias[n + 1]; }
            if (m < M) {
                float2 v = make_float2(acc[mf][nf][0] + b0, acc[mf][nf][1] + b1);
                *reinterpret_cast<float2*>(C + (long long)m * ldc + n) = v;
            }
            if (m + 8 < M) {
                float2 v = make_float2(acc[mf][nf][2] + b0, acc[mf][nf][3] + b1);
                *reinterpret_cast<float2*>(C + (long long)(m + 8) * ldc + n) = v;
            }
        }
    }
}

// =================== persistent recurrence kernel v5 (tensor cores) =========
// 128 CTAs = 4 bg(32 batch rows) x 32 cg(16 out cols). 256 threads = 8 warps
// (2 m-frags x 4 k-slices). Batch-group-LOCAL barriers (32-CTA fan-in).
// P rows prefetched to smem in the same cp.async group as h0.

#define RNN_CTAS 128
#define RNN_THR 256
#define WT16 16384
#define HT32 32768
#define OFF_W 0
#define OFF_H0 (6 * WT16)
#define OFF_H1 (OFF_H0 + 2 * HT32)
#define OFF_P (OFF_H1 + 2 * HT32)         // 229376: P prefetch, 32x16 fp32
#define RNN_SMEM (OFF_P + 2048)           // 231424 (<= 232448 opt-in)
#define OFF_R OFF_H0
#define REDSTR 17

__global__ __launch_bounds__(RNN_THR, 1)
void rnn_persist(const int* __restrict__ inputs,
                 const float* __restrict__ W0,
                 const float* __restrict__ b0,
                 const float* __restrict__ Wl,
                 const float* __restrict__ bl,
                 float* __restrict__ hfin) {
    extern __shared__ char smc[];
    const uint32_t sbase = smem_u32(smc);
    float* const smf = reinterpret_cast<float*>(smc);
    const int tid = threadIdx.x;
    const int wid = tid >> 5, lid = tid & 31;
    const int bg = blockIdx.x >> 5;
    const int cg = blockIdx.x & 31;
    const int cbase = cg * 16;

    // ---- split weight slices into smem bf16 hi/lo tiles (once, swizzled) ----
    for (int i = tid; i < 16 * 512; i += RNN_THR) {
        const int r = i >> 9, k = i & 511;
        const int gc = cbase + r;
        const uint32_t off = r * 1024 + (((k >> 3) ^ (r & 7)) << 4) + (k & 7) * 2;
        float v[3];
        v[0] = W0[gc * 1024 + k];
        v[1] = Wl[gc * 1024 + 512 + k];
        v[2] = Wl[gc * 1024 + k];
#pragma unroll
        for (int t = 0; t < 3; t++) {
            const __nv_bfloat16 hi = __float2bfloat16(v[t]);
            const __nv_bfloat16 lo = __float2bfloat16(v[t] - __bfloat162float(hi));
            char* base = smc + OFF_W + (2 * t) * WT16 + off;
            *reinterpret_cast<__nv_bfloat16*>(base) = hi;
            *reinterpret_cast<__nv_bfloat16*>(base + WT16) = lo;
        }
    }
    __syncthreads();

    const int mw = wid & 1;
    const int kw = wid >> 1;
    const int lr = lid & 15, lc = lid >> 4;

    const int ecoll = tid & 15, erow = tid >> 4;
    const int ecol = cbase + ecoll;
    const float b0c = b0[ecol], blc = bl[ecol];

    const int arow = mw * 16 + lr;
    const uint32_t aRowH0 = sbase + OFF_H0 + arow * 1024;
    const uint32_t aRowH1 = sbase + OFF_H1 + arow * 1024;
    const uint32_t bRow = sbase + OFF_W + lr * 1024;
    const int axor = arow & 7;
    const int bxor = lr & 7;
    const int c0 = kw * 16 + lc;

    unsigned int* const gbar = &g_sync4[bg * 32];   // 128B-spaced counters

    auto stage_h = [&](uint32_t offBase, const __nv_bfloat16* hi,
                       const __nv_bfloat16* lo) {
#pragma unroll
        for (int j = 0; j < 16; j++) {
            const int idx = tid + j * 256;
            const int tile = idx >> 11;
            const int c = idx & 2047;
            const int row = c >> 6, ch = c & 63;
            const __nv_bfloat16* src =
                (tile ? lo : hi) + (long long)(bg * 32 + row) * HH + ch * 8;
            const uint32_t dst = sbase + offBase + tile * HT32 + row * 1024 +
                                 ((ch ^ (row & 7)) << 4);
            asm volatile("cp.async.cg.shared.global [%0], [%1], 16;"
                         :: "r"(dst), "l"(src) : "memory");
        }
        asm volatile("cp.async.commit_group;" ::: "memory");
    };

    for (int p = 0; p <= SS; p++) {
        float acc0[2][4] = {{0, 0, 0, 0}, {0, 0, 0, 0}};
        float acc1[2][4] = {{0, 0, 0, 0}, {0, 0, 0, 0}};

        // prefetch P rows for this phase's tokens (joins h0's commit group)
        if (p < SS && tid < 128) {
            const int row = tid >> 2, ch = tid & 3;
            const int tok = __ldg(inputs + p * BB + bg * 32 + row);
            const float* src = g_P + (long long)tok * HH + cbase + ch * 4;
            const uint32_t dst = sbase + OFF_P + row * 64 + ch * 16;
            asm volatile("cp.async.cg.shared.global [%0], [%1], 16;"
                         :: "r"(dst), "l"(src) : "memory");
        }
        stage_h(OFF_H0, g_h0bh[(p + 1) & 1], g_h0bl[(p + 1) & 1]);   // group 0 (P+h0)
        stage_h(OFF_H1, g_h1bh[p & 1], g_h1bl[p & 1]);               // group 1
        asm volatile("cp.async.wait_group 1;" ::: "memory");         // P+h0 ready
        __syncthreads();

        // ---- pass A: h0 x W0h -> acc0 ; h0 x Wlx -> acc1 ----
#pragma unroll
        for (int i = 0; i < 8; i++) {
            const uint32_t sc = (uint32_t)((c0 + i * 2) ^ axor) << 4;
            const uint32_t wc = (uint32_t)((c0 + i * 2) ^ bxor) << 4;
            uint32_t ah[4], al[4], b0h[4], b0l[4], bxh[4], bxl[4];
            ldm_x4(aRowH0 + sc, ah);
            ldm_x4(aRowH0 + HT32 + sc, al);
            ldm_x4(bRow + 0 * WT16 + wc, b0h);
            ldm_x4(bRow + 1 * WT16 + wc, b0l);
            ldm_x4(bRow + 2 * WT16 + wc, bxh);
            ldm_x4(bRow + 3 * WT16 + wc, bxl);
            mma_bf16(acc0[0], ah, b0h[0], b0h[2]);
            mma_bf16(acc0[1], ah, b0h[1], b0h[3]);
            mma_bf16(acc0[0], ah, b0l[0], b0l[2]);
            mma_bf16(acc0[1], ah, b0l[1], b0l[3]);
            mma_bf16(acc0[0], al, b0h[0], b0h[2]);
            mma_bf16(acc0[1], al, b0h[1], b0h[3]);
            mma_bf16(acc1[0], ah, bxh[0], bxh[2]);
            mma_bf16(acc1[1], ah, bxh[1], bxh[3]);
            mma_bf16(acc1[0], ah, bxl[0], bxl[2]);
            mma_bf16(acc1[1], ah, bxl[1], bxl[3]);
            mma_bf16(acc1[0], al, bxh[0], bxh[2]);
            mma_bf16(acc1[1], al, bxh[1], bxh[3]);
        }

        asm volatile("cp.async.wait_group 0;" ::: "memory");   // h1 ready
        __syncthreads();

        // ---- pass B: h1 x Wlh -> acc1 ----
#pragma unroll
        for (int i = 0; i < 8; i++) {
            const uint32_t sc = (uint32_t)((c0 + i * 2) ^ axor) << 4;
            const uint32_t wc = (uint32_t)((c0 + i * 2) ^ bxor) << 4;
            uint32_t ah[4], al[4], bhh[4], bhl[4];
            ldm_x4(aRowH1 + sc, ah);
            ldm_x4(aRowH1 + HT32 + sc, al);
            ldm_x4(bRow + 4 * WT16 + wc, bhh);
            ldm_x4(bRow + 5 * WT16 + wc, bhl);
            mma_bf16(acc1[0], ah, bhh[0], bhh[2]);
            mma_bf16(acc1[1], ah, bhh[1], bhh[3]);
            mma_bf16(acc1[0], ah, bhl[0], bhl[2]);
            mma_bf16(acc1[1], ah, bhl[1], bhl[3]);
            mma_bf16(acc1[0], al, bhh[0], bhh[2]);
            mma_bf16(acc1[1], al, bhh[1], bhh[3]);
        }

        // ---- write k-slice frags to red (aliases h0 buffer) ----
        {
            const int rg = lid >> 2, cc = (lid & 3) * 2;
            float* red = smf + OFF_R / 4;
            const int m = mw * 16 + rg;
#pragma unroll
            for (int nf = 0; nf < 2; nf++) {
                const int n = nf * 8 + cc;
                float* r0 = red + ((0 * 4 + kw) * 32 + m) * REDSTR + n;
                float* r1 = red + ((1 * 4 + kw) * 32 + m) * REDSTR + n;
                r0[0] = acc0[nf][0]; r0[1] = acc0[nf][1];
                r0[8 * REDSTR] = acc0[nf][2]; r0[8 * REDSTR + 1] = acc0[nf][3];
                r1[0] = acc1[nf][0]; r1[1] = acc1[nf][1];
                r1[8 * REDSTR] = acc1[nf][2]; r1[8 * REDSTR + 1] = acc1[nf][3];
            }
        }
        __syncthreads();

        // ---- epilogue: reduce, tanh, store h state; arrive; then tops ----
        __nv_bfloat16 hv1s[2], lv1s[2];
        {
            float* red = smf + OFF_R / 4;
            const float* smP = smf + OFF_P / 4;
#pragma unroll
            for (int e = 0; e < 2; e++) {
                const int row = erow + e * 16;
                const int gbr = bg * 32 + row;
                float s0 = 0.f, s1 = 0.f;
#pragma unroll
                for (int q = 0; q < 4; q++) {
                    s0 += red[((0 * 4 + q) * 32 + row) * REDSTR + ecoll];
                    s1 += red[((1 * 4 + q) * 32 + row) * REDSTR + ecoll];
                }
                const long long o = (long long)gbr * HH + ecol;
                if (p < SS) {
                    const float v = tanhf(s0 + smP[row * 16 + ecoll] + b0c);
                    const __nv_bfloat16 hv = __float2bfloat16(v);
                    const __nv_bfloat16 lv = __float2bfloat16(v - __bfloat162float(hv));
                    g_h0bh[p & 1][o] = hv;
                    g_h0bl[p & 1][o] = lv;
                    if (p == SS - 1) hfin[o] = v;
                }
                if (p >= 1) {
                    const float v = tanhf(s1 + blc);
                    const __nv_bfloat16 hv = __float2bfloat16(v);
                    const __nv_bfloat16 lv = __float2bfloat16(v - __bfloat162float(hv));
                    g_h1bh[(p + 1) & 1][o] = hv;
                    g_h1bl[(p + 1) & 1][o] = lv;
                    hv1s[e] = hv; lv1s[e] = lv;
                    if (p == SS) hfin[BB * HH + o] = v;
                }
            }
        }

        // arrive on the bg-local barrier BEFORE the tops stores
        if (p < SS) {
            __syncthreads();
            if (tid == 0) {
                asm volatile("red.release.gpu.global.add.u32 [%0], 1;"
                             :: "l"(gbar) : "memory");
            }
        }

        if (p >= 1) {
            const int s = p - 1;
#pragma unroll
            for (int e = 0; e < 2; e++) {
                const int gbr = bg * 32 + erow + e * 16;
                const long long ot = ((long long)s * BB + gbr) * HH + ecol;
                g_Thi[ot] = hv1s[e];
                g_Tlo[ot] = lv1s[e];
            }
        }

        if (p < SS) {
            if (tid == 0) {
                const unsigned int target = (unsigned)(p + 1) * 32;
                unsigned int v;
                do {
                    asm volatile("ld.acquire.gpu.global.u32 %0, [%1];"
                                 : "=r"(v) : "l"(gbar) : "memory");
                } while (v < target);
            }
            __syncthreads();
        }
    }
}

// ---------------- prep kernels -----------------------------------------------
__global__ void prep_w0x(const float* __restrict__ W0) {
    int idx = blockIdx.x * blockDim.x + threadIdx.x;
    if (idx >= HH * EE) return;
    int c = idx / EE;
    int e = idx % EE;
    float v = W0[c * (HH + EE) + HH + e];
    __nv_bfloat16 hi = __float2bfloat16(v);
    g_Xhi[c * EE + e] = hi;
    g_Xlo[c * EE + e] = __float2bfloat16(v - __bfloat162float(hi));
}

__global__ void split_arr(const float* __restrict__ src, __nv_bfloat16* __restrict__ hi,
                          __nv_bfloat16* __restrict__ lo, int n, float scale) {
    int i = blockIdx.x * blockDim.x + threadIdx.x;
    if (i >= n) return;
    float v = src[i] * scale;
    __nv_bfloat16 h = __float2bfloat16(v);
    hi[i] = h;
    lo[i] = __float2bfloat16(v - __bfloat162float(h));
}

__global__ void init_state(const float* __restrict__ hidden) {
    int i = blockIdx.x * blockDim.x + threadIdx.x;
    if (i < 128) g_sync4[i] = 0;
    if (i < BB * HH) {
        float v0 = hidden[i];
        __nv_bfloat16 h0 = __float2bfloat16(v0);
        g_h0bh[1][i] = h0;
        g_h0bl[1][i] = __float2bfloat16(v0 - __bfloat162float(h0));
        float v1 = hidden[BB * HH + i];
        __nv_bfloat16 h1 = __float2bfloat16(v1);
        g_h1bh[1][i] = h1;
        g_h1bl[1][i] = __float2bfloat16(v1 - __bfloat162float(h1));
    }
}

// ---------------- launch ------------------------------------------------------
extern "C" void kernel_launch(void* const* d_in, const int* in_sizes, int n_in,
                              void* d_out, int out_size) {
    const int*   inputs = (const int*)  d_in[0];
    const float* hidden = (const float*)d_in[1];
    const float* emb    = (const float*)d_in[2];
    const float* W0     = (const float*)d_in[3];
    const float* b0     = (const float*)d_in[4];
    const float* Wl     = (const float*)d_in[5];
    const float* bl     = (const float*)d_in[6];
    const float* Wout   = (const float*)d_in[7];
    const float* bout   = (const float*)d_in[8];

    float* logits = (float*)d_out;
    float* hfin   = (float*)d_out + (long long)SS * BB * VV;

    cudaFuncSetAttribute(gemm_hmma, cudaFuncAttributeMaxDynamicSharedMemorySize,
                         GEMM_SMEM);
    cudaFuncSetAttribute(rnn_persist, cudaFuncAttributeMaxDynamicSharedMemorySize,
                         RNN_SMEM);

    float* pP = nullptr;
    cudaGetSymbolAddress((void**)&pP, g_P);
    __nv_bfloat16 *pThi, *pTlo, *pWhi, *pWlo, *pEhi, *pElo, *pXhi, *pXlo;
    cudaGetSymbolAddress((void**)&pThi, g_Thi);
    cudaGetSymbolAddress((void**)&pTlo, g_Tlo);
    cudaGetSymbolAddress((void**)&pWhi, g_Whi);
    cudaGetSymbolAddress((void**)&pWlo, g_Wlo);
    cudaGetSymbolAddress((void**)&pEhi, g_Ehi);
    cudaGetSymbolAddress((void**)&pElo, g_Elo);
    cudaGetSymbolAddress((void**)&pXhi, g_Xhi);
    cudaGetSymbolAddress((void**)&pXlo, g_Xlo);

    const float scale = 22.62741699796952f;  // sqrt(512)

    // 1. prep
    init_state<<<(BB * HH + 255) / 256, 256>>>(hidden);
    prep_w0x<<<(HH * EE + 255) / 256, 256>>>(W0);
    split_arr<<<(VV * EE + 255) / 256, 256>>>(emb, pEhi, pElo, VV * EE, scale);
    split_arr<<<(VV * HH + 255) / 256, 256>>>(Wout, pWhi, pWlo, VV * HH, 1.0f);

    // 2. P = scale*emb @ W0x^T  (M=10000, N=512, K=512)
    {
        dim3 grid((HH + 127) / 128, (VV + 127) / 128);
        gemm_hmma<<<grid, 256, GEMM_SMEM>>>(pEhi, pElo, pXhi, pXlo,
                                            VV, HH, pP, HH, nullptr);
    }

    // 3. full recurrence in ONE persistent kernel (tensor cores)
    rnn_persist<<<RNN_CTAS, RNN_THR, RNN_SMEM>>>(inputs, W0, b0, Wl, bl, hfin);

    // 4. logits = tops @ Wout^T + bout  (M=16384, N=10000, K=512)
    {
        dim3 grid((VV + 127) / 128, (SS * BB + 127) / 128);
        gemm_hmma<<<grid, 256, GEMM_SMEM>>>(pThi, pTlo, pWhi, pWlo,
                                            SS * BB, VV, logits, VV, bout);
    }
}